// round 2
// baseline (speedup 1.0000x reference)
#include <cuda_runtime.h>

#define BB 16
#define DD 64
#define NN 256
#define RR 32
#define HDIM 128
#define STEPS 5
#define NP 257              // padded smem pitch (bank-conflict-free)
#define W2P 132             // padded W2^T pitch (16B-aligned rows, conflict-lite)
#define UNI 16640           // union scratch region, floats
#define BDN (BB*DD*NN)

// ---------------- device globals (scratch; no allocations allowed) -----------
__device__ float g_x[2][BDN];          // state ping-pong, layout [b][d][n]
__device__ float g_M[RR*DD*DD];        // Wq Wk^T per rule
__device__ float g_u[RR*DD];           // Wq bk
__device__ float g_v[RR*DD];           // Wk bq  (i.e. bq^T Wk)
__device__ float g_c[RR];              // bq . bk
__device__ float g_gate[BB*RR];
__device__ float g_t[(size_t)RR*BDN];  // per-rule weighted deltas [r][b][d][n]

// ---------------- init: symbols (B,D,H,W) == (B,D,N) → x0 --------------------
__global__ void k_init(const float* __restrict__ sym) {
    int i = blockIdx.x * 256 + threadIdx.x;
    g_x[0][i] = sym[i];
}

// ---------------- precompute M = Wq Wk^T -------------------------------------
__global__ void k_precM(const float* __restrict__ Wq, const float* __restrict__ Wk) {
    int i = blockIdx.x * 256 + threadIdx.x;     // over R*D*D
    int d2 = i & 63, d1 = (i >> 6) & 63, r = i >> 12;
    const float* a = Wq + (r*DD + d1) * HDIM;
    const float* bkk = Wk + (r*DD + d2) * HDIM;
    float s = 0.f;
#pragma unroll 8
    for (int h = 0; h < HDIM; h++) s = fmaf(a[h], bkk[h], s);
    g_M[i] = s;
}

__global__ void k_precUVC(const float* __restrict__ Wq, const float* __restrict__ bq,
                          const float* __restrict__ Wk, const float* __restrict__ bk) {
    int r = blockIdx.x, d = threadIdx.x;        // 32 blocks x 64 threads
    float su = 0.f, sv = 0.f;
    const float* wqr = Wq + (r*DD + d) * HDIM;
    const float* wkr = Wk + (r*DD + d) * HDIM;
    const float* bqr = bq + r * HDIM;
    const float* bkr = bk + r * HDIM;
#pragma unroll 8
    for (int h = 0; h < HDIM; h++) {
        su = fmaf(wqr[h], bkr[h], su);
        sv = fmaf(bqr[h], wkr[h], sv);
    }
    g_u[r*DD + d] = su;
    g_v[r*DD + d] = sv;
    if (d == 0) {
        float sc = 0.f;
        for (int h = 0; h < HDIM; h++) sc = fmaf(bqr[h], bkr[h], sc);
        g_c[r] = sc;
    }
}

// ---------------- gate: g = softmax(relu(mean(x) Wg1 + bg1) Wg2 + bg2) -------
__global__ void k_gate(int cur, const float* __restrict__ Wg1, const float* __restrict__ bg1,
                       const float* __restrict__ Wg2, const float* __restrict__ bg2) {
    __shared__ float pooled[DD];
    __shared__ float hbuf[HDIM];
    int b = blockIdx.x, t = threadIdx.x;        // 128 threads
    const float* x = g_x[cur] + (size_t)b * DD * NN;
    if (t < DD) {
        float s = 0.f;
        const float* row = x + t * NN;
#pragma unroll 8
        for (int n = 0; n < NN; n++) s += row[n];
        pooled[t] = s * (1.0f / NN);
    }
    __syncthreads();
    {
        float acc = bg1[t];
#pragma unroll 8
        for (int d = 0; d < DD; d++) acc = fmaf(pooled[d], Wg1[d*HDIM + t], acc);
        hbuf[t] = fmaxf(acc, 0.f);
    }
    __syncthreads();
    if (t < RR) {
        float lg = bg2[t];
#pragma unroll 8
        for (int j = 0; j < HDIM; j++) lg = fmaf(hbuf[j], Wg2[j*RR + t], lg);
        float m = lg;
#pragma unroll
        for (int o = 16; o > 0; o >>= 1) m = fmaxf(m, __shfl_xor_sync(0xffffffffu, m, o));
        float e = __expf(lg - m);
        float ssum = e;
#pragma unroll
        for (int o = 16; o > 0; o >>= 1) ssum += __shfl_xor_sync(0xffffffffu, ssum, o);
        g_gate[b*RR + t] = e / ssum;
    }
}

// ---------------- fused per-(b,r) rule kernel --------------------------------
// Phase A: sx = x M (+ e,f dot terms)        → cxT
// Phase B: S = sx x^T (+e+f+c)*scale, softmax, ctx = A x   (ctx overwrites cxT)
// Phase C: t = relu(ctx W1 + b1) W2 + b2 ; g_t = gate * t
__global__ void __launch_bounds__(256, 1)
k_rule(int cur, const float* __restrict__ W1g, const float* __restrict__ b1g,
       const float* __restrict__ W2g, const float* __restrict__ b2g) {
    extern __shared__ float sm[];
    float* xT  = sm;                 // DD*NP   x tile, [d][n] padded
    float* cxT = sm + DD*NP;         // DD*NP   sx then ctx, [d][n] padded
    float* uni = sm + 2*DD*NP;       // UNI floats, phase-dependent:
    float* Ms   = uni;               //   A/B: 4096  (M, 64x64)
    float* Arow = uni + 4096;        //   B:   4096  (8 warps x 2 rows x 256)
    float* eS   = uni + 8192;        //   B:   256
    float* fS   = uni + 8448;        //   B:   256
    float* W1s  = uni;               //   C:   8192  (64x128)
    float* W2sT = uni + 8192;        //   C:   64*W2P (W2 transposed, padded)

    const int t = threadIdx.x;
    const int r = blockIdx.x & (RR - 1);
    const int b = blockIdx.x >> 5;
    const float* xg = g_x[cur] + (size_t)b * DD * NN;

    for (int i = t; i < DD*NN; i += 256) {
        int d = i >> 8, n = i & 255;
        xT[d*NP + n] = xg[i];
    }
    for (int i = t; i < DD*DD; i += 256) Ms[i] = g_M[r*DD*DD + i];
    __syncthreads();

    // ---------------- Phase A: thread n computes sx[n][:] --------------------
    {
        const int n = t;
        float acc[DD];
#pragma unroll
        for (int j = 0; j < DD; j++) acc[j] = 0.f;
        float ea = 0.f, fa = 0.f;
        const float* ur = g_u + r*DD;
        const float* vr = g_v + r*DD;
#pragma unroll 1
        for (int d = 0; d < DD; d++) {
            float xv = xT[d*NP + n];
            ea = fmaf(xv, ur[d], ea);
            fa = fmaf(xv, vr[d], fa);
            const float4* m4 = (const float4*)(Ms + d*DD);
#pragma unroll
            for (int j4 = 0; j4 < DD/4; j4++) {
                float4 mv = m4[j4];
                acc[4*j4+0] = fmaf(xv, mv.x, acc[4*j4+0]);
                acc[4*j4+1] = fmaf(xv, mv.y, acc[4*j4+1]);
                acc[4*j4+2] = fmaf(xv, mv.z, acc[4*j4+2]);
                acc[4*j4+3] = fmaf(xv, mv.w, acc[4*j4+3]);
            }
        }
#pragma unroll
        for (int j = 0; j < DD; j++) cxT[j*NP + n] = acc[j];
        eS[n] = ea;
        fS[n] = fa;
    }
    __syncthreads();

    // ---------------- Phase B: attention, 2 query rows per warp iteration ----
    {
        const int w = t >> 5, l = t & 31;
        const float cc = g_c[r];
        const float scl = 0.088388347648318447f;   // 1/sqrt(128)
        float* A0 = Arow + (w*2 + 0) * NN;
        float* A1 = Arow + (w*2 + 1) * NN;
#pragma unroll 1
        for (int ii = 0; ii < 16; ii++) {
            int n0 = w*32 + ii*2, n1 = n0 + 1;
            float sa[8], sb[8];
#pragma unroll
            for (int j = 0; j < 8; j++) { sa[j] = 0.f; sb[j] = 0.f; }
#pragma unroll 1
            for (int d = 0; d < DD; d++) {
                float s0 = cxT[d*NP + n0];
                float s1 = cxT[d*NP + n1];
                const float* xr = xT + d*NP + l;
#pragma unroll
                for (int j = 0; j < 8; j++) {
                    float xv = xr[j*32];
                    sa[j] = fmaf(s0, xv, sa[j]);
                    sb[j] = fmaf(s1, xv, sb[j]);
                }
            }
            float e0 = eS[n0], e1 = eS[n1];
            float mx0 = -1e30f, mx1 = -1e30f;
#pragma unroll
            for (int j = 0; j < 8; j++) {
                float fm = fS[l + j*32] + cc;
                sa[j] = (sa[j] + e0 + fm) * scl;
                sb[j] = (sb[j] + e1 + fm) * scl;
                mx0 = fmaxf(mx0, sa[j]);
                mx1 = fmaxf(mx1, sb[j]);
            }
#pragma unroll
            for (int o = 16; o > 0; o >>= 1) {
                mx0 = fmaxf(mx0, __shfl_xor_sync(0xffffffffu, mx0, o));
                mx1 = fmaxf(mx1, __shfl_xor_sync(0xffffffffu, mx1, o));
            }
            float sum0 = 0.f, sum1 = 0.f;
#pragma unroll
            for (int j = 0; j < 8; j++) {
                sa[j] = __expf(sa[j] - mx0); sum0 += sa[j];
                sb[j] = __expf(sb[j] - mx1); sum1 += sb[j];
            }
#pragma unroll
            for (int o = 16; o > 0; o >>= 1) {
                sum0 += __shfl_xor_sync(0xffffffffu, sum0, o);
                sum1 += __shfl_xor_sync(0xffffffffu, sum1, o);
            }
            float i0 = 1.f/sum0, i1 = 1.f/sum1;
#pragma unroll
            for (int j = 0; j < 8; j++) {
                A0[l + j*32] = sa[j] * i0;
                A1[l + j*32] = sb[j] * i1;
            }
            __syncwarp();
            // ctx rows n0,n1 for d = l and l+32 (overwrite cxT columns n0,n1)
            float c00 = 0.f, c01 = 0.f, c10 = 0.f, c11 = 0.f;
            const float* x0 = xT + l*NP;
            const float* x1 = xT + (l+32)*NP;
#pragma unroll 1
            for (int m4 = 0; m4 < NN/4; m4++) {
                float4 a0 = ((const float4*)A0)[m4];
                float4 a1 = ((const float4*)A1)[m4];
                int m = 4*m4;
                float x00 = x0[m], x01 = x0[m+1], x02 = x0[m+2], x03 = x0[m+3];
                float x10 = x1[m], x11 = x1[m+1], x12 = x1[m+2], x13 = x1[m+3];
                c00 = fmaf(a0.x, x00, c00); c00 = fmaf(a0.y, x01, c00);
                c00 = fmaf(a0.z, x02, c00); c00 = fmaf(a0.w, x03, c00);
                c01 = fmaf(a0.x, x10, c01); c01 = fmaf(a0.y, x11, c01);
                c01 = fmaf(a0.z, x12, c01); c01 = fmaf(a0.w, x13, c01);
                c10 = fmaf(a1.x, x00, c10); c10 = fmaf(a1.y, x01, c10);
                c10 = fmaf(a1.z, x02, c10); c10 = fmaf(a1.w, x03, c10);
                c11 = fmaf(a1.x, x10, c11); c11 = fmaf(a1.y, x11, c11);
                c11 = fmaf(a1.z, x12, c11); c11 = fmaf(a1.w, x13, c11);
            }
            __syncwarp();
            cxT[l*NP + n0]      = c00;
            cxT[(l+32)*NP + n0] = c01;
            cxT[l*NP + n1]      = c10;
            cxT[(l+32)*NP + n1] = c11;
        }
    }
    __syncthreads();

    // ---------------- Phase C: MLP, thread n owns one row --------------------
    for (int i = t; i < DD*HDIM; i += 256) W1s[i] = W1g[r*DD*HDIM + i];
    for (int i = t; i < HDIM*DD; i += 256) {
        int j = i >> 6, d = i & 63;
        W2sT[d*W2P + j] = W2g[r*HDIM*DD + i];
    }
    __syncthreads();
    {
        const int n = t;
        const float gr = g_gate[b*RR + r];
        const float* b1r = b1g + r*HDIM;
        const float* b2r = b2g + r*DD;
        float hv[HDIM];
#pragma unroll
        for (int j = 0; j < HDIM; j++) hv[j] = b1r[j];
#pragma unroll 1
        for (int d = 0; d < DD; d++) {
            float cv = cxT[d*NP + n];
            const float4* w4 = (const float4*)(W1s + d*HDIM);
#pragma unroll
            for (int j4 = 0; j4 < HDIM/4; j4++) {
                float4 wv = w4[j4];
                hv[4*j4+0] = fmaf(cv, wv.x, hv[4*j4+0]);
                hv[4*j4+1] = fmaf(cv, wv.y, hv[4*j4+1]);
                hv[4*j4+2] = fmaf(cv, wv.z, hv[4*j4+2]);
                hv[4*j4+3] = fmaf(cv, wv.w, hv[4*j4+3]);
            }
        }
#pragma unroll
        for (int j = 0; j < HDIM; j++) hv[j] = fmaxf(hv[j], 0.f);
        float* outp = g_t + ((size_t)(r*BB + b)) * DD * NN;
#pragma unroll 1
        for (int d = 0; d < DD; d++) {
            float acc = b2r[d];
            const float4* w4 = (const float4*)(W2sT + d*W2P);
#pragma unroll
            for (int j4 = 0; j4 < HDIM/4; j4++) {
                float4 wv = w4[j4];
                acc = fmaf(hv[4*j4+0], wv.x, acc);
                acc = fmaf(hv[4*j4+1], wv.y, acc);
                acc = fmaf(hv[4*j4+2], wv.z, acc);
                acc = fmaf(hv[4*j4+3], wv.w, acc);
            }
            __stcg(outp + d*NN + n, gr * acc);
        }
    }
}

// ---------------- deterministic reduction over rules + residual --------------
__global__ void k_reduce(int cur) {
    int i = blockIdx.x * 256 + threadIdx.x;     // over [b][d][n]
    float s = g_x[cur][i];
#pragma unroll
    for (int rr = 0; rr < RR; rr++) s += __ldg(&g_t[(size_t)rr * BDN + i]);
    g_x[cur ^ 1][i] = s;
}

// ---------------- writeback (x layout == output layout (B,D,H,W)) ------------
__global__ void k_out(int cur, float* __restrict__ out) {
    int i = blockIdx.x * 256 + threadIdx.x;
    out[i] = g_x[cur][i];
}

// ---------------- launch -----------------------------------------------------
extern "C" void kernel_launch(void* const* d_in, const int* in_sizes, int n_in,
                              void* d_out, int out_size) {
    const float* sym = (const float*)d_in[0];
    const float* Wq  = (const float*)d_in[1];
    const float* bq  = (const float*)d_in[2];
    const float* Wk  = (const float*)d_in[3];
    const float* bk  = (const float*)d_in[4];
    const float* W1  = (const float*)d_in[5];
    const float* b1  = (const float*)d_in[6];
    const float* W2  = (const float*)d_in[7];
    const float* b2  = (const float*)d_in[8];
    const float* Wg1 = (const float*)d_in[13];
    const float* bg1 = (const float*)d_in[14];
    const float* Wg2 = (const float*)d_in[15];
    const float* bg2 = (const float*)d_in[16];
    float* out = (float*)d_out;

    const size_t SMEM_BYTES = (size_t)(2*DD*NP + UNI) * sizeof(float);  // 198144
    static int smem_set = 0;
    if (!smem_set) {
        cudaFuncSetAttribute(k_rule, cudaFuncAttributeMaxDynamicSharedMemorySize,
                             (int)SMEM_BYTES);
        smem_set = 1;
    }

    k_init<<<BDN/256, 256>>>(sym);
    k_precM<<<(RR*DD*DD)/256, 256>>>(Wq, Wk);
    k_precUVC<<<RR, DD>>>(Wq, bq, Wk, bk);

    int cur = 0;
    for (int s = 0; s < STEPS; s++) {
        k_gate<<<BB, 128>>>(cur, Wg1, bg1, Wg2, bg2);
        k_rule<<<BB*RR, 256, SMEM_BYTES>>>(cur, W1, b1, W2, b2);
        k_reduce<<<BDN/256, 256>>>(cur);
        cur ^= 1;
    }
    k_out<<<BDN/256, 256>>>(cur, out);
}

// round 3
// speedup vs baseline: 3.4565x; 3.4565x over previous
#include <cuda_runtime.h>
#include <cstdint>

#define BB 16
#define DD 64
#define NN 256
#define RR 32
#define HDIM 128
#define STEPS 5
#define BDN (BB*DD*NN)

// smem pitches (floats) — chosen for conflict-free mma fragment loads
#define NP   264   // xT [d][n]            (8 mod 32)
#define SXP  68    // sx/ctx [n][d]        (4 mod 32)
#define PP   68    // P [n][m-local]
#define W1P  136   // W1 [d][h]            (8 mod 32)
#define W2P  72    // W2 [h][d]            (8 mod 32)
#define MP   72    // M  [d][d']
#define HP   12    // per-warp H block [32][8]

// float offsets in dynamic smem
#define OFF_XT   0
#define OFF_SX   16896
#define OFF_R3   34304              // M | P | (W1,W2)
#define OFF_W1   OFF_R3
#define OFF_W2   (OFF_R3 + 8704)
#define OFF_E    52224
#define OFF_F    52480
#define OFF_U    52736
#define OFF_V    52800
#define OFF_POOL 52864
#define OFF_HID  52928
#define OFF_GATE 53056
#define OFF_H    53088              // 8 warps * 32*HP = 3072
#define SMEM_FLOATS 56192           // 224768 bytes

// ---------------- device globals -------------------------------------------
__device__ float g_x[2][BDN];          // state, layout [b][n][d]
__device__ float g_M[RR*DD*DD];        // Wq Wk^T per rule
__device__ float g_u[RR*DD];           // Wq bk
__device__ float g_v[RR*DD];           // Wk bq
__device__ float g_c[RR];              // bq . bk
__device__ float g_t[(size_t)RR*BDN];  // per-rule deltas [r][b][n][d]

// ---------------- helpers ---------------------------------------------------
__device__ __forceinline__ uint32_t f2tf(float x) {
    uint32_t u; asm("cvt.rna.tf32.f32 %0, %1;" : "=r"(u) : "f"(x)); return u;
}
__device__ __forceinline__ float tfr(float x) { return __uint_as_float(f2tf(x)); }

__device__ __forceinline__ void mma8(float* c, const uint32_t* a,
                                     uint32_t b0, uint32_t b1) {
    asm volatile("mma.sync.aligned.m16n8k8.row.col.f32.tf32.tf32.f32 "
        "{%0,%1,%2,%3}, {%4,%5,%6,%7}, {%8,%9}, {%0,%1,%2,%3};"
        : "+f"(c[0]), "+f"(c[1]), "+f"(c[2]), "+f"(c[3])
        : "r"(a[0]), "r"(a[1]), "r"(a[2]), "r"(a[3]), "r"(b0), "r"(b1));
}

// ---------------- init: symbols [b][d][n] -> g_x[0] as [b][n][d] -------------
__global__ void k_init(const float* __restrict__ sym) {
    int i = blockIdx.x * 256 + threadIdx.x;
    int b = i >> 14, rem = i & 16383, n = rem >> 6, d = rem & 63;
    g_x[0][i] = sym[b*16384 + d*256 + n];
}

// ---------------- precompute M = Wq Wk^T ------------------------------------
__global__ void k_precM(const float* __restrict__ Wq, const float* __restrict__ Wk) {
    int i = blockIdx.x * 256 + threadIdx.x;
    int d2 = i & 63, d1 = (i >> 6) & 63, r = i >> 12;
    const float* a = Wq + (r*DD + d1) * HDIM;
    const float* bkk = Wk + (r*DD + d2) * HDIM;
    float s = 0.f;
#pragma unroll 8
    for (int h = 0; h < HDIM; h++) s = fmaf(a[h], bkk[h], s);
    g_M[i] = s;
}

__global__ void k_precUVC(const float* __restrict__ Wq, const float* __restrict__ bq,
                          const float* __restrict__ Wk, const float* __restrict__ bk) {
    int r = blockIdx.x, d = threadIdx.x;
    float su = 0.f, sv = 0.f;
    const float* wqr = Wq + (r*DD + d) * HDIM;
    const float* wkr = Wk + (r*DD + d) * HDIM;
    const float* bqr = bq + r * HDIM;
    const float* bkr = bk + r * HDIM;
#pragma unroll 8
    for (int h = 0; h < HDIM; h++) {
        su = fmaf(wqr[h], bkr[h], su);
        sv = fmaf(bqr[h], wkr[h], sv);
    }
    g_u[r*DD + d] = su;
    g_v[r*DD + d] = sv;
    if (d == 0) {
        float sc = 0.f;
        for (int h = 0; h < HDIM; h++) sc = fmaf(bqr[h], bkr[h], sc);
        g_c[r] = sc;
    }
}

// ---------------- fused per-(b,r) rule kernel (tf32 tensor cores) -----------
__global__ void __launch_bounds__(256, 1)
k_rule(int cur,
       const float* __restrict__ W1g, const float* __restrict__ b1g,
       const float* __restrict__ W2g, const float* __restrict__ b2g,
       const float* __restrict__ Wg1, const float* __restrict__ bg1,
       const float* __restrict__ Wg2, const float* __restrict__ bg2) {
    extern __shared__ float sm[];
    float* xT    = sm + OFF_XT;
    float* sxb   = sm + OFF_SX;     // sx, later ctx
    float* r3    = sm + OFF_R3;     // M (A) | P (B) | W1/W2 (C)
    float* W1s   = sm + OFF_W1;
    float* W2s   = sm + OFF_W2;
    float* eS    = sm + OFF_E;
    float* fS    = sm + OFF_F;
    float* uS    = sm + OFF_U;
    float* vS    = sm + OFF_V;
    float* poolS = sm + OFF_POOL;
    float* hidS  = sm + OFF_HID;
    float* gateS = sm + OFF_GATE;
    float* Hw    = sm + OFF_H + (threadIdx.x >> 5) * (32 * HP);

    const int t = threadIdx.x;
    const int lane = t & 31, w = t >> 5;
    const int g = lane >> 2, t4 = lane & 3;
    const int r = blockIdx.x & (RR - 1), b = blockIdx.x >> 5;
    const int row0 = w * 32;

    const float* xg = g_x[cur] + (size_t)b * NN * DD;

    // ---- prologue: stage x (transposed), M, u, v ---------------------------
    for (int i = t; i < NN*DD; i += 256) {
        int n = i >> 6, d = i & 63;
        xT[d*NP + n] = tfr(xg[i]);
    }
    for (int i = t; i < DD*DD; i += 256)
        r3[(i >> 6)*MP + (i & 63)] = tfr(g_M[r*DD*DD + i]);
    if (t < DD) { uS[t] = g_u[r*DD + t]; vS[t] = g_v[r*DD + t]; }
    __syncthreads();

    // ---- e/f per token, pooled per channel ---------------------------------
    {
        float ea = 0.f, fa = 0.f;
#pragma unroll 8
        for (int d = 0; d < DD; d++) {
            float xv = xT[d*NP + t];
            ea = fmaf(xv, uS[d], ea);
            fa = fmaf(xv, vS[d], fa);
        }
        eS[t] = ea; fS[t] = fa;
        int d = t >> 2, q = t & 3;
        float s = 0.f;
        const float* rowp = xT + d*NP + q*64;
#pragma unroll 8
        for (int n = 0; n < 64; n++) s += rowp[n];
        s += __shfl_xor_sync(~0u, s, 1);
        s += __shfl_xor_sync(~0u, s, 2);
        if (q == 0) poolS[d] = s * (1.f/NN);
    }
    __syncthreads();
    // ---- gate MLP (fused, redundant per block: ~24 KFLOP) ------------------
    if (t < HDIM) {
        float acc = bg1[t];
#pragma unroll 8
        for (int d = 0; d < DD; d++) acc = fmaf(poolS[d], __ldg(&Wg1[d*HDIM + t]), acc);
        hidS[t] = fmaxf(acc, 0.f);
    }
    __syncthreads();
    if (t < RR) {
        float lg = bg2[t];
#pragma unroll 8
        for (int j = 0; j < HDIM; j++) lg = fmaf(hidS[j], __ldg(&Wg2[j*RR + t]), lg);
        float m = lg;
#pragma unroll
        for (int o = 16; o > 0; o >>= 1) m = fmaxf(m, __shfl_xor_sync(~0u, m, o));
        float e = __expf(lg - m), ss = e;
#pragma unroll
        for (int o = 16; o > 0; o >>= 1) ss += __shfl_xor_sync(~0u, ss, o);
        gateS[t] = e / ss;
    }

    // ---- Phase A: sx = X @ M  (mma, warp rows [row0,row0+32)) --------------
    float SA[2][8][4];
#pragma unroll
    for (int mt = 0; mt < 2; mt++)
#pragma unroll
        for (int nt = 0; nt < 8; nt++)
#pragma unroll
            for (int i = 0; i < 4; i++) SA[mt][nt][i] = 0.f;
#pragma unroll 1
    for (int k0 = 0; k0 < DD; k0 += 8) {
        uint32_t a[2][4];
#pragma unroll
        for (int mt = 0; mt < 2; mt++) {
            const float* p = xT + (k0 + t4)*NP + row0 + mt*16 + g;
            a[mt][0] = __float_as_uint(p[0]);
            a[mt][1] = __float_as_uint(p[8]);
            a[mt][2] = __float_as_uint(p[4*NP]);
            a[mt][3] = __float_as_uint(p[4*NP + 8]);
        }
#pragma unroll
        for (int nt = 0; nt < 8; nt++) {
            const float* q = r3 + (k0 + t4)*MP + nt*8 + g;
            uint32_t b0 = __float_as_uint(q[0]);
            uint32_t b1 = __float_as_uint(q[4*MP]);
            mma8(SA[0][nt], a[0], b0, b1);
            mma8(SA[1][nt], a[1], b0, b1);
        }
    }
#pragma unroll
    for (int mt = 0; mt < 2; mt++)
#pragma unroll
        for (int nt = 0; nt < 8; nt++) {
            int rr0 = row0 + mt*16 + g, c0 = nt*8 + 2*t4;
            sxb[rr0*SXP + c0]       = tfr(SA[mt][nt][0]);
            sxb[rr0*SXP + c0 + 1]   = tfr(SA[mt][nt][1]);
            sxb[(rr0+8)*SXP + c0]   = tfr(SA[mt][nt][2]);
            sxb[(rr0+8)*SXP + c0+1] = tfr(SA[mt][nt][3]);
        }
    __syncthreads();   // M dead -> r3 becomes P

    // ---- Phase B: flash attention over 4 col-blocks ------------------------
    float CA[2][8][4];
    float Mrw[2][2], Lrw[2][2];
#pragma unroll
    for (int mt = 0; mt < 2; mt++)
#pragma unroll
        for (int nt = 0; nt < 8; nt++)
#pragma unroll
            for (int i = 0; i < 4; i++) CA[mt][nt][i] = 0.f;
#pragma unroll
    for (int mt = 0; mt < 2; mt++)
#pragma unroll
        for (int hb = 0; hb < 2; hb++) { Mrw[mt][hb] = -1e30f; Lrw[mt][hb] = 0.f; }
    const float cc = g_c[r];
    const float scl = 0.08838834764831845f;  // 1/sqrt(128)
    float* Pb = r3;
#pragma unroll 1
    for (int j = 0; j < 4; j++) {
        const int mb = j * 64;
#pragma unroll
        for (int mt = 0; mt < 2; mt++)
#pragma unroll
            for (int nt = 0; nt < 8; nt++)
#pragma unroll
                for (int i = 0; i < 4; i++) SA[mt][nt][i] = 0.f;
        // S block = sx @ X^T
#pragma unroll 1
        for (int k0 = 0; k0 < DD; k0 += 8) {
            uint32_t a[2][4];
#pragma unroll
            for (int mt = 0; mt < 2; mt++) {
                const float* p = sxb + (row0 + mt*16 + g)*SXP + k0 + t4;
                a[mt][0] = __float_as_uint(p[0]);
                a[mt][1] = __float_as_uint(p[8*SXP]);
                a[mt][2] = __float_as_uint(p[4]);
                a[mt][3] = __float_as_uint(p[8*SXP + 4]);
            }
#pragma unroll
            for (int nt = 0; nt < 8; nt++) {
                const float* q = xT + (k0 + t4)*NP + mb + nt*8 + g;
                uint32_t b0 = __float_as_uint(q[0]);
                uint32_t b1 = __float_as_uint(q[4*NP]);
                mma8(SA[0][nt], a[0], b0, b1);
                mma8(SA[1][nt], a[1], b0, b1);
            }
        }
        // bias + online softmax (per owned row)
#pragma unroll
        for (int mt = 0; mt < 2; mt++)
#pragma unroll
            for (int hb = 0; hb < 2; hb++) {
                int rowi = row0 + mt*16 + hb*8 + g;
                float er = eS[rowi];
                float mx = -1e30f;
#pragma unroll
                for (int nt = 0; nt < 8; nt++)
#pragma unroll
                    for (int i2 = 0; i2 < 2; i2++) {
                        float fv = fS[mb + nt*8 + 2*t4 + i2];
                        float v = (SA[mt][nt][hb*2 + i2] + er + fv + cc) * scl;
                        SA[mt][nt][hb*2 + i2] = v;
                        mx = fmaxf(mx, v);
                    }
                mx = fmaxf(mx, __shfl_xor_sync(~0u, mx, 1));
                mx = fmaxf(mx, __shfl_xor_sync(~0u, mx, 2));
                float Mn = fmaxf(Mrw[mt][hb], mx);
                float sc = __expf(Mrw[mt][hb] - Mn);
                Mrw[mt][hb] = Mn;
                float ls = 0.f;
#pragma unroll
                for (int nt = 0; nt < 8; nt++)
#pragma unroll
                    for (int i2 = 0; i2 < 2; i2++) {
                        float p = __expf(SA[mt][nt][hb*2 + i2] - Mn);
                        SA[mt][nt][hb*2 + i2] = p;
                        ls += p;
                    }
                ls += __shfl_xor_sync(~0u, ls, 1);
                ls += __shfl_xor_sync(~0u, ls, 2);
                Lrw[mt][hb] = Lrw[mt][hb]*sc + ls;
#pragma unroll
                for (int nt = 0; nt < 8; nt++) {
                    CA[mt][nt][hb*2]     *= sc;
                    CA[mt][nt][hb*2 + 1] *= sc;
                }
            }
        // write P block (warp-private rows)
#pragma unroll
        for (int mt = 0; mt < 2; mt++)
#pragma unroll
            for (int nt = 0; nt < 8; nt++) {
                int rr0 = row0 + mt*16 + g, c0 = nt*8 + 2*t4;
                Pb[rr0*PP + c0]       = tfr(SA[mt][nt][0]);
                Pb[rr0*PP + c0 + 1]   = tfr(SA[mt][nt][1]);
                Pb[(rr0+8)*PP + c0]   = tfr(SA[mt][nt][2]);
                Pb[(rr0+8)*PP + c0+1] = tfr(SA[mt][nt][3]);
            }
        __syncwarp();
        // CTX += P @ X(rows mb..mb+63)
#pragma unroll 1
        for (int k0 = 0; k0 < 64; k0 += 8) {
            uint32_t a[2][4];
#pragma unroll
            for (int mt = 0; mt < 2; mt++) {
                const float* p = Pb + (row0 + mt*16 + g)*PP + k0 + t4;
                a[mt][0] = __float_as_uint(p[0]);
                a[mt][1] = __float_as_uint(p[8*PP]);
                a[mt][2] = __float_as_uint(p[4]);
                a[mt][3] = __float_as_uint(p[8*PP + 4]);
            }
#pragma unroll
            for (int nt = 0; nt < 8; nt++) {
                const float* q = xT + (nt*8 + g)*NP + mb + k0 + t4;
                uint32_t b0 = __float_as_uint(q[0]);
                uint32_t b1 = __float_as_uint(q[4]);
                mma8(CA[0][nt], a[0], b0, b1);
                mma8(CA[1][nt], a[1], b0, b1);
            }
        }
        __syncwarp();
    }
    // normalize ctx, store to sxb (sx dead)
#pragma unroll
    for (int mt = 0; mt < 2; mt++) {
        float i0 = 1.f / Lrw[mt][0], i1 = 1.f / Lrw[mt][1];
#pragma unroll
        for (int nt = 0; nt < 8; nt++) {
            int rr0 = row0 + mt*16 + g, c0 = nt*8 + 2*t4;
            sxb[rr0*SXP + c0]       = tfr(CA[mt][nt][0] * i0);
            sxb[rr0*SXP + c0 + 1]   = tfr(CA[mt][nt][1] * i0);
            sxb[(rr0+8)*SXP + c0]   = tfr(CA[mt][nt][2] * i1);
            sxb[(rr0+8)*SXP + c0+1] = tfr(CA[mt][nt][3] * i1);
        }
    }
    __syncthreads();   // P dead -> r3 becomes W1/W2
    for (int i = t; i < DD*HDIM; i += 256)
        W1s[(i >> 7)*W1P + (i & 127)] = tfr(__ldg(&W1g[r*DD*HDIM + i]));
    for (int i = t; i < HDIM*DD; i += 256)
        W2s[(i >> 6)*W2P + (i & 63)] = tfr(__ldg(&W2g[r*HDIM*DD + i]));
    __syncthreads();

    // ---- Phase C: T = relu(ctx@W1 + b1)@W2, h-chunked ----------------------
    float TA[2][8][4];
#pragma unroll
    for (int mt = 0; mt < 2; mt++)
#pragma unroll
        for (int nt = 0; nt < 8; nt++)
#pragma unroll
            for (int i = 0; i < 4; i++) TA[mt][nt][i] = 0.f;
#pragma unroll 1
    for (int hk = 0; hk < 16; hk++) {
        const int h0 = hk * 8;
        float HA[2][4];
#pragma unroll
        for (int mt = 0; mt < 2; mt++)
#pragma unroll
            for (int i = 0; i < 4; i++) HA[mt][i] = 0.f;
#pragma unroll 1
        for (int k0 = 0; k0 < DD; k0 += 8) {
            uint32_t a[2][4];
#pragma unroll
            for (int mt = 0; mt < 2; mt++) {
                const float* p = sxb + (row0 + mt*16 + g)*SXP + k0 + t4;
                a[mt][0] = __float_as_uint(p[0]);
                a[mt][1] = __float_as_uint(p[8*SXP]);
                a[mt][2] = __float_as_uint(p[4]);
                a[mt][3] = __float_as_uint(p[8*SXP + 4]);
            }
            const float* q = W1s + (k0 + t4)*W1P + h0 + g;
            uint32_t b0 = __float_as_uint(q[0]);
            uint32_t b1 = __float_as_uint(q[4*W1P]);
            mma8(HA[0], a[0], b0, b1);
            mma8(HA[1], a[1], b0, b1);
        }
        {
            int hcol = h0 + 2*t4;
            float bia0 = __ldg(&b1g[r*HDIM + hcol]);
            float bia1 = __ldg(&b1g[r*HDIM + hcol + 1]);
#pragma unroll
            for (int mt = 0; mt < 2; mt++) {
                Hw[(mt*16 + g)*HP + 2*t4]       = tfr(fmaxf(HA[mt][0] + bia0, 0.f));
                Hw[(mt*16 + g)*HP + 2*t4 + 1]   = tfr(fmaxf(HA[mt][1] + bia1, 0.f));
                Hw[(mt*16 + 8 + g)*HP + 2*t4]   = tfr(fmaxf(HA[mt][2] + bia0, 0.f));
                Hw[(mt*16 + 8 + g)*HP + 2*t4+1] = tfr(fmaxf(HA[mt][3] + bia1, 0.f));
            }
        }
        __syncwarp();
        {
            uint32_t a[2][4];
#pragma unroll
            for (int mt = 0; mt < 2; mt++) {
                const float* p = Hw + (mt*16 + g)*HP + t4;
                a[mt][0] = __float_as_uint(p[0]);
                a[mt][1] = __float_as_uint(p[8*HP]);
                a[mt][2] = __float_as_uint(p[4]);
                a[mt][3] = __float_as_uint(p[8*HP + 4]);
            }
#pragma unroll
            for (int nt = 0; nt < 8; nt++) {
                const float* q = W2s + (h0 + t4)*W2P + nt*8 + g;
                uint32_t b0 = __float_as_uint(q[0]);
                uint32_t b1 = __float_as_uint(q[4*W2P]);
                mma8(TA[0][nt], a[0], b0, b1);
                mma8(TA[1][nt], a[1], b0, b1);
            }
        }
        __syncwarp();
    }
    // ---- epilogue: g_t[r][b][n][d] = gate * (T + b2) -----------------------
    const float gv = gateS[r];
    float* outp = g_t + ((size_t)(r*BB + b)) * DD * NN;
#pragma unroll
    for (int mt = 0; mt < 2; mt++)
#pragma unroll
        for (int nt = 0; nt < 8; nt++) {
            int d0 = nt*8 + 2*t4;
            float b20 = __ldg(&b2g[r*DD + d0]);
            float b21 = __ldg(&b2g[r*DD + d0 + 1]);
            int n0 = row0 + mt*16 + g;
            float2 v0 = make_float2((TA[mt][nt][0] + b20)*gv, (TA[mt][nt][1] + b21)*gv);
            float2 v1 = make_float2((TA[mt][nt][2] + b20)*gv, (TA[mt][nt][3] + b21)*gv);
            *(float2*)(outp + n0*DD + d0)       = v0;
            *(float2*)(outp + (n0 + 8)*DD + d0) = v1;
        }
}

// ---------------- deterministic reduction over rules + residual --------------
__global__ void k_reduce(int cur) {
    int i = blockIdx.x * 256 + threadIdx.x;
    float s = g_x[cur][i];
#pragma unroll
    for (int rr = 0; rr < RR; rr++) s += __ldg(&g_t[(size_t)rr * BDN + i]);
    g_x[cur ^ 1][i] = s;
}

// ---------------- writeback: [b][n][d] -> output [b][d][n] -------------------
__global__ void k_out(int cur, float* __restrict__ out) {
    int i = blockIdx.x * 256 + threadIdx.x;
    int b = i >> 14, rem = i & 16383, n = rem >> 6, d = rem & 63;
    out[b*16384 + d*256 + n] = g_x[cur][i];
}

// ---------------- launch -----------------------------------------------------
extern "C" void kernel_launch(void* const* d_in, const int* in_sizes, int n_in,
                              void* d_out, int out_size) {
    const float* sym = (const float*)d_in[0];
    const float* Wq  = (const float*)d_in[1];
    const float* bq  = (const float*)d_in[2];
    const float* Wk  = (const float*)d_in[3];
    const float* bk  = (const float*)d_in[4];
    const float* W1  = (const float*)d_in[5];
    const float* b1  = (const float*)d_in[6];
    const float* W2  = (const float*)d_in[7];
    const float* b2  = (const float*)d_in[8];
    const float* Wg1 = (const float*)d_in[13];
    const float* bg1 = (const float*)d_in[14];
    const float* Wg2 = (const float*)d_in[15];
    const float* bg2 = (const float*)d_in[16];
    float* out = (float*)d_out;

    const size_t SMEM_BYTES = (size_t)SMEM_FLOATS * sizeof(float);  // 224768
    static int smem_set = 0;
    if (!smem_set) {
        cudaFuncSetAttribute(k_rule, cudaFuncAttributeMaxDynamicSharedMemorySize,
                             (int)SMEM_BYTES);
        smem_set = 1;
    }

    k_init<<<BDN/256, 256>>>(sym);
    k_precM<<<(RR*DD*DD)/256, 256>>>(Wq, Wk);
    k_precUVC<<<RR, DD>>>(Wq, bq, Wk, bk);

    int cur = 0;
    for (int s = 0; s < STEPS; s++) {
        k_rule<<<BB*RR, 256, SMEM_BYTES>>>(cur, W1, b1, W2, b2, Wg1, bg1, Wg2, bg2);
        k_reduce<<<BDN/256, 256>>>(cur);
        cur ^= 1;
    }
    k_out<<<BDN/256, 256>>>(cur, out);
}

// round 4
// speedup vs baseline: 4.9529x; 1.4329x over previous
#include <cuda_runtime.h>
#include <cuda_bf16.h>
#include <cstdint>

#define BB 16
#define DD 64
#define NN 256
#define RR 32
#define HDIM 128
#define STEPS 5
#define BDN (BB*DD*NN)

// bf16 smem pitches (elements). Byte pitch mod 128 == 16 (or 48) -> ldmatrix
// 8-lane phases hit 8 distinct 16B bank groups.
#define XT_P 264   // 528 B
#define XN_P 72    // 144 B
#define SX_P 72
#define MT_P 72
#define PB_P 72
#define W1_P 72
#define W2_P 136   // 272 B
#define HW_P 24    // 48 B

// byte offsets into dynamic smem (all 16B aligned)
#define OFF_XT  0                       // 64 x 264 bf16   = 33792
#define OFF_XN  33792                   // 256 x 72        = 36864
#define OFF_SX  70656                   // 256 x 72        = 36864 (sx, then ctx)
#define OFF_R3  107520                  // union: Mt | P | W1t+W2t (36864)
#define OFF_W2T (OFF_R3 + 18432)
#define OFF_HW  144384                  // 16 warps x 16 x 24 bf16 = 12288
#define OFF_E   156672
#define OFF_F   157696
#define OFF_U   158720
#define OFF_V   158976
#define OFF_PL  159232
#define OFF_HI  159488
#define OFF_GT  160000
#define SMEM_BYTES 160128

// ---------------- device globals -------------------------------------------
__device__ float g_x[2][BDN];          // state, layout [b][n][d], fp32
__device__ float g_M[RR*DD*DD];        // Wq Wk^T per rule
__device__ float g_u[RR*DD];           // Wq bk
__device__ float g_v[RR*DD];           // Wk bq
__device__ float g_c[RR];              // bq . bk
__device__ float g_t[(size_t)RR*BDN];  // per-rule deltas [r][b][n][d]

// ---------------- helpers ---------------------------------------------------
__device__ __forceinline__ void ldsm4(uint32_t& r0, uint32_t& r1,
                                      uint32_t& r2, uint32_t& r3, uint32_t sa) {
    asm volatile("ldmatrix.sync.aligned.m8n8.x4.shared.b16 {%0,%1,%2,%3}, [%4];"
        : "=r"(r0), "=r"(r1), "=r"(r2), "=r"(r3) : "r"(sa));
}
__device__ __forceinline__ void mma16(float* c, uint32_t a0, uint32_t a1,
                                      uint32_t a2, uint32_t a3,
                                      uint32_t b0, uint32_t b1) {
    asm volatile("mma.sync.aligned.m16n8k16.row.col.f32.bf16.bf16.f32 "
        "{%0,%1,%2,%3}, {%4,%5,%6,%7}, {%8,%9}, {%0,%1,%2,%3};"
        : "+f"(c[0]), "+f"(c[1]), "+f"(c[2]), "+f"(c[3])
        : "r"(a0), "r"(a1), "r"(a2), "r"(a3), "r"(b0), "r"(b1));
}
__device__ __forceinline__ uint32_t pbf2(float lo, float hi) {
    __nv_bfloat162 h = __floats2bfloat162_rn(lo, hi);
    return *reinterpret_cast<uint32_t*>(&h);
}

// ---------------- init: symbols [b][d][n] -> g_x[0] as [b][n][d] -------------
__global__ void k_init(const float* __restrict__ sym) {
    int i = blockIdx.x * 256 + threadIdx.x;
    int b = i >> 14, rem = i & 16383, n = rem >> 6, d = rem & 63;
    g_x[0][i] = sym[b*16384 + d*256 + n];
}

// ---------------- precompute M = Wq Wk^T ------------------------------------
__global__ void k_precM(const float* __restrict__ Wq, const float* __restrict__ Wk) {
    int i = blockIdx.x * 256 + threadIdx.x;
    int d2 = i & 63, d1 = (i >> 6) & 63, r = i >> 12;
    const float* a = Wq + (r*DD + d1) * HDIM;
    const float* bkk = Wk + (r*DD + d2) * HDIM;
    float s = 0.f;
#pragma unroll 8
    for (int h = 0; h < HDIM; h++) s = fmaf(a[h], bkk[h], s);
    g_M[i] = s;
}

__global__ void k_precUVC(const float* __restrict__ Wq, const float* __restrict__ bq,
                          const float* __restrict__ Wk, const float* __restrict__ bk) {
    int r = blockIdx.x, d = threadIdx.x;
    float su = 0.f, sv = 0.f;
    const float* wqr = Wq + (r*DD + d) * HDIM;
    const float* wkr = Wk + (r*DD + d) * HDIM;
    const float* bqr = bq + r * HDIM;
    const float* bkr = bk + r * HDIM;
#pragma unroll 8
    for (int h = 0; h < HDIM; h++) {
        su = fmaf(wqr[h], bkr[h], su);
        sv = fmaf(bqr[h], wkr[h], sv);
    }
    g_u[r*DD + d] = su;
    g_v[r*DD + d] = sv;
    if (d == 0) {
        float sc = 0.f;
        for (int h = 0; h < HDIM; h++) sc = fmaf(bqr[h], bkr[h], sc);
        g_c[r] = sc;
    }
}

// ---------------- fused per-(b,r) rule kernel (bf16 mma + ldmatrix) ----------
__global__ void __launch_bounds__(512, 1)
k_rule(int cur,
       const float* __restrict__ W1g, const float* __restrict__ b1g,
       const float* __restrict__ W2g, const float* __restrict__ b2g,
       const float* __restrict__ Wg1, const float* __restrict__ bg1,
       const float* __restrict__ Wg2, const float* __restrict__ bg2) {
    extern __shared__ char smb[];
    const uint32_t sbu = (uint32_t)__cvta_generic_to_shared(smb);
    __nv_bfloat16* xTb  = (__nv_bfloat16*)(smb + OFF_XT);
    __nv_bfloat16* xNb  = (__nv_bfloat16*)(smb + OFF_XN);
    __nv_bfloat16* Mtb  = (__nv_bfloat16*)(smb + OFF_R3);
    __nv_bfloat16* Pbb  = (__nv_bfloat16*)(smb + OFF_R3);
    __nv_bfloat16* W1tb = (__nv_bfloat16*)(smb + OFF_R3);
    __nv_bfloat16* W2tb = (__nv_bfloat16*)(smb + OFF_W2T);
    float* eS    = (float*)(smb + OFF_E);
    float* fS    = (float*)(smb + OFF_F);
    float* uS    = (float*)(smb + OFF_U);
    float* vS    = (float*)(smb + OFF_V);
    float* poolS = (float*)(smb + OFF_PL);
    float* hidS  = (float*)(smb + OFF_HI);
    float* gateS = (float*)(smb + OFF_GT);

    const int t = threadIdx.x;
    const int lane = t & 31, w = t >> 5;
    const int g = lane >> 2, t4 = lane & 3;
    const int r = blockIdx.x & (RR - 1), b = blockIdx.x >> 5;
    const int row0 = w * 16;

    // lane-dependent ldmatrix row/k offsets
    const int aRow = lane & 15;                            // A x4: rows 0-15
    const int aKof = (lane >> 4) << 3;                     // A x4: k 0 / 8
    const int bRow = (lane & 7) + ((lane >> 4) << 3);      // B x4: rows 0-15
    const int bKof = ((lane >> 3) & 1) << 3;               // B x4: k 0 / 8

    const float* xg = g_x[cur] + (size_t)b * NN * DD;

    // ---- prologue: stage x in both layouts, Mt, u, v -----------------------
    for (int j = t; j < NN*DD/2; j += 512) {
        int n = j >> 5, d2 = (j & 31) * 2;
        float v0 = xg[n*DD + d2], v1 = xg[n*DD + d2 + 1];
        *(uint32_t*)(smb + OFF_XN + (n*XN_P + d2)*2) = pbf2(v0, v1);
        xTb[d2*XT_P + n]     = __float2bfloat16_rn(v0);
        xTb[(d2+1)*XT_P + n] = __float2bfloat16_rn(v1);
    }
    for (int i = t; i < DD*DD; i += 512) {
        int d1 = i >> 6, d2 = i & 63;
        Mtb[d2*MT_P + d1] = __float2bfloat16_rn(g_M[r*DD*DD + i]);
    }
    if (t < DD) { uS[t] = g_u[r*DD + t]; vS[t] = g_v[r*DD + t]; }
    __syncthreads();

    // ---- e/f per token (warps 0-7), pooled mean (warps 8-15) ---------------
    if (t < NN) {
        float ea = 0.f, fa = 0.f;
#pragma unroll 8
        for (int d = 0; d < DD; d++) {
            float xv = __bfloat162float(xNb[t*XN_P + d]);
            ea = fmaf(xv, uS[d], ea);
            fa = fmaf(xv, vS[d], fa);
        }
        eS[t] = ea; fS[t] = fa;
    } else {
        int idx = t - NN, d = idx >> 2, q = idx & 3;
        float s = 0.f;
#pragma unroll 8
        for (int n = q*64; n < q*64 + 64; n++) s += __bfloat162float(xNb[n*XN_P + d]);
        s += __shfl_xor_sync(~0u, s, 1);
        s += __shfl_xor_sync(~0u, s, 2);
        if (q == 0) poolS[d] = s * (1.f/NN);
    }
    __syncthreads();
    if (t < HDIM) {
        float acc = bg1[t];
#pragma unroll 8
        for (int d = 0; d < DD; d++) acc = fmaf(poolS[d], __ldg(&Wg1[d*HDIM + t]), acc);
        hidS[t] = fmaxf(acc, 0.f);
    }
    __syncthreads();
    if (t < RR) {
        float lg = bg2[t];
#pragma unroll 8
        for (int j = 0; j < HDIM; j++) lg = fmaf(hidS[j], __ldg(&Wg2[j*RR + t]), lg);
        float m = lg;
#pragma unroll
        for (int o = 16; o > 0; o >>= 1) m = fmaxf(m, __shfl_xor_sync(~0u, m, o));
        float e = __expf(lg - m), ss = e;
#pragma unroll
        for (int o = 16; o > 0; o >>= 1) ss += __shfl_xor_sync(~0u, ss, o);
        gateS[t] = e / ss;   // consumed after the W-staging __syncthreads
    }

    // ---- Phase A: sx = X @ M  (warp rows [row0,row0+16)) -------------------
    {
        float SA[8][4];
#pragma unroll
        for (int nt = 0; nt < 8; nt++)
#pragma unroll
            for (int i = 0; i < 4; i++) SA[nt][i] = 0.f;
#pragma unroll
        for (int k0 = 0; k0 < DD; k0 += 16) {
            uint32_t a0, a1, a2, a3;
            ldsm4(a0, a1, a2, a3,
                  sbu + OFF_XN + ((row0 + aRow)*XN_P + k0 + aKof)*2);
#pragma unroll
            for (int p = 0; p < 4; p++) {
                uint32_t b0, b1, b2, b3;
                ldsm4(b0, b1, b2, b3,
                      sbu + OFF_R3 + ((p*16 + bRow)*MT_P + k0 + bKof)*2);
                mma16(SA[2*p],   a0, a1, a2, a3, b0, b1);
                mma16(SA[2*p+1], a0, a1, a2, a3, b2, b3);
            }
        }
#pragma unroll
        for (int nt = 0; nt < 8; nt++) {
            int c0 = nt*8 + 2*t4;
            *(uint32_t*)(smb + OFF_SX + ((row0 + g)*SX_P + c0)*2)     = pbf2(SA[nt][0], SA[nt][1]);
            *(uint32_t*)(smb + OFF_SX + ((row0 + 8 + g)*SX_P + c0)*2) = pbf2(SA[nt][2], SA[nt][3]);
        }
    }
    __syncthreads();   // Mt dead -> region becomes P

    // ---- Phase B: flash attention over 4 key-blocks of 64 ------------------
    {
        float CA[8][4];
        float Mr[2] = {-1e30f, -1e30f}, Lr[2] = {0.f, 0.f};
#pragma unroll
        for (int nt = 0; nt < 8; nt++)
#pragma unroll
            for (int i = 0; i < 4; i++) CA[nt][i] = 0.f;
        const float cc = g_c[r];
        const float scl = 0.08838834764831845f;  // 1/sqrt(128)
#pragma unroll 1
        for (int j = 0; j < 4; j++) {
            const int mb = j * 64;
            float SA[8][4];
#pragma unroll
            for (int nt = 0; nt < 8; nt++)
#pragma unroll
                for (int i = 0; i < 4; i++) SA[nt][i] = 0.f;
            // S = sx @ X^T (block cols mb..mb+63)
#pragma unroll
            for (int k0 = 0; k0 < DD; k0 += 16) {
                uint32_t a0, a1, a2, a3;
                ldsm4(a0, a1, a2, a3,
                      sbu + OFF_SX + ((row0 + aRow)*SX_P + k0 + aKof)*2);
#pragma unroll
                for (int p = 0; p < 4; p++) {
                    uint32_t b0, b1, b2, b3;
                    ldsm4(b0, b1, b2, b3,
                          sbu + OFF_XN + ((mb + p*16 + bRow)*XN_P + k0 + bKof)*2);
                    mma16(SA[2*p],   a0, a1, a2, a3, b0, b1);
                    mma16(SA[2*p+1], a0, a1, a2, a3, b2, b3);
                }
            }
            // bias + online softmax
#pragma unroll
            for (int hb = 0; hb < 2; hb++) {
                float er = eS[row0 + hb*8 + g] + cc;
                float mx = -1e30f;
#pragma unroll
                for (int nt = 0; nt < 8; nt++)
#pragma unroll
                    for (int i2 = 0; i2 < 2; i2++) {
                        float v = (SA[nt][hb*2 + i2] + er
                                   + fS[mb + nt*8 + 2*t4 + i2]) * scl;
                        SA[nt][hb*2 + i2] = v;
                        mx = fmaxf(mx, v);
                    }
                mx = fmaxf(mx, __shfl_xor_sync(~0u, mx, 1));
                mx = fmaxf(mx, __shfl_xor_sync(~0u, mx, 2));
                float Mn = fmaxf(Mr[hb], mx);
                float rs = __expf(Mr[hb] - Mn);
                Mr[hb] = Mn;
                float ls = 0.f;
#pragma unroll
                for (int nt = 0; nt < 8; nt++)
#pragma unroll
                    for (int i2 = 0; i2 < 2; i2++) {
                        float p = __expf(SA[nt][hb*2 + i2] - Mn);
                        SA[nt][hb*2 + i2] = p;
                        ls += p;
                    }
                ls += __shfl_xor_sync(~0u, ls, 1);
                ls += __shfl_xor_sync(~0u, ls, 2);
                Lr[hb] = Lr[hb]*rs + ls;
#pragma unroll
                for (int nt = 0; nt < 8; nt++) {
                    CA[nt][hb*2]     *= rs;
                    CA[nt][hb*2 + 1] *= rs;
                }
            }
            // write P (warp-private 16 rows)
#pragma unroll
            for (int nt = 0; nt < 8; nt++) {
                int c0 = nt*8 + 2*t4;
                *(uint32_t*)(smb + OFF_R3 + ((row0 + g)*PB_P + c0)*2)     = pbf2(SA[nt][0], SA[nt][1]);
                *(uint32_t*)(smb + OFF_R3 + ((row0 + 8 + g)*PB_P + c0)*2) = pbf2(SA[nt][2], SA[nt][3]);
            }
            __syncwarp();
            // CTX += P @ X(rows mb..mb+63)  (B from xT[d][m])
#pragma unroll
            for (int k0 = 0; k0 < 64; k0 += 16) {
                uint32_t a0, a1, a2, a3;
                ldsm4(a0, a1, a2, a3,
                      sbu + OFF_R3 + ((row0 + aRow)*PB_P + k0 + aKof)*2);
#pragma unroll
                for (int p = 0; p < 4; p++) {
                    uint32_t b0, b1, b2, b3;
                    ldsm4(b0, b1, b2, b3,
                          sbu + OFF_XT + ((p*16 + bRow)*XT_P + mb + k0 + bKof)*2);
                    mma16(CA[2*p],   a0, a1, a2, a3, b0, b1);
                    mma16(CA[2*p+1], a0, a1, a2, a3, b2, b3);
                }
            }
            __syncwarp();
        }
        // normalize ctx, overwrite sx (owner-warp rows only)
        float i0 = 1.f / Lr[0], i1 = 1.f / Lr[1];
#pragma unroll
        for (int nt = 0; nt < 8; nt++) {
            int c0 = nt*8 + 2*t4;
            *(uint32_t*)(smb + OFF_SX + ((row0 + g)*SX_P + c0)*2)     = pbf2(CA[nt][0]*i0, CA[nt][1]*i0);
            *(uint32_t*)(smb + OFF_SX + ((row0 + 8 + g)*SX_P + c0)*2) = pbf2(CA[nt][2]*i1, CA[nt][3]*i1);
        }
    }
    __syncthreads();   // P dead -> region becomes W1t/W2t

    for (int i = t; i < DD*HDIM; i += 512) {
        int d = i >> 7, h = i & 127;
        W1tb[h*W1_P + d] = __float2bfloat16_rn(__ldg(&W1g[r*DD*HDIM + i]));
    }
    for (int i = t; i < HDIM*DD; i += 512) {
        int h = i >> 6, d = i & 63;
        W2tb[d*W2_P + h] = __float2bfloat16_rn(__ldg(&W2g[r*HDIM*DD + i]));
    }
    __syncthreads();

    // ---- Phase C: T = relu(ctx@W1 + b1)@W2, 16-h chunks --------------------
    {
        const uint32_t hwbase = sbu + OFF_HW + w * (16*HW_P*2);
        char* hwgen = smb + OFF_HW + w * (16*HW_P*2);
        float TA[8][4];
#pragma unroll
        for (int nt = 0; nt < 8; nt++)
#pragma unroll
            for (int i = 0; i < 4; i++) TA[nt][i] = 0.f;
#pragma unroll 1
        for (int ck = 0; ck < 8; ck++) {
            const int h0 = ck * 16;
            float HA[2][4];
#pragma unroll
            for (int q = 0; q < 2; q++)
#pragma unroll
                for (int i = 0; i < 4; i++) HA[q][i] = 0.f;
#pragma unroll
            for (int k0 = 0; k0 < DD; k0 += 16) {
                uint32_t a0, a1, a2, a3, b0, b1, b2, b3;
                ldsm4(a0, a1, a2, a3,
                      sbu + OFF_SX + ((row0 + aRow)*SX_P + k0 + aKof)*2);
                ldsm4(b0, b1, b2, b3,
                      sbu + OFF_R3 + ((h0 + bRow)*W1_P + k0 + bKof)*2);
                mma16(HA[0], a0, a1, a2, a3, b0, b1);
                mma16(HA[1], a0, a1, a2, a3, b2, b3);
            }
#pragma unroll
            for (int q = 0; q < 2; q++) {
                int hc = h0 + q*8 + 2*t4;
                float bb0 = __ldg(&b1g[r*HDIM + hc]);
                float bb1 = __ldg(&b1g[r*HDIM + hc + 1]);
                *(uint32_t*)(hwgen + (g*HW_P + q*8 + 2*t4)*2) =
                    pbf2(fmaxf(HA[q][0] + bb0, 0.f), fmaxf(HA[q][1] + bb1, 0.f));
                *(uint32_t*)(hwgen + ((8 + g)*HW_P + q*8 + 2*t4)*2) =
                    pbf2(fmaxf(HA[q][2] + bb0, 0.f), fmaxf(HA[q][3] + bb1, 0.f));
            }
            __syncwarp();
            {
                uint32_t a0, a1, a2, a3;
                ldsm4(a0, a1, a2, a3, hwbase + (aRow*HW_P + aKof)*2);
#pragma unroll
                for (int p = 0; p < 4; p++) {
                    uint32_t b0, b1, b2, b3;
                    ldsm4(b0, b1, b2, b3,
                          sbu + OFF_W2T + ((p*16 + bRow)*W2_P + h0 + bKof)*2);
                    mma16(TA[2*p],   a0, a1, a2, a3, b0, b1);
                    mma16(TA[2*p+1], a0, a1, a2, a3, b2, b3);
                }
            }
            __syncwarp();
        }
        // ---- epilogue: g_t[r][b][n][d] = gate * (T + b2) -------------------
        const float gv = gateS[r];
        float* outp = g_t + ((size_t)(r*BB + b)) * DD * NN;
#pragma unroll
        for (int nt = 0; nt < 8; nt++) {
            int d0 = nt*8 + 2*t4;
            float b20 = __ldg(&b2g[r*DD + d0]);
            float b21 = __ldg(&b2g[r*DD + d0 + 1]);
            float2 v0 = make_float2((TA[nt][0] + b20)*gv, (TA[nt][1] + b21)*gv);
            float2 v1 = make_float2((TA[nt][2] + b20)*gv, (TA[nt][3] + b21)*gv);
            *(float2*)(outp + (row0 + g)*DD + d0)     = v0;
            *(float2*)(outp + (row0 + 8 + g)*DD + d0) = v1;
        }
    }
}

// ---------------- deterministic reduction over rules + residual --------------
__global__ void k_reduce(int cur) {
    int i = blockIdx.x * 256 + threadIdx.x;
    float s = g_x[cur][i];
#pragma unroll
    for (int rr = 0; rr < RR; rr++) s += __ldg(&g_t[(size_t)rr * BDN + i]);
    g_x[cur ^ 1][i] = s;
}

// ---------------- writeback: [b][n][d] -> output [b][d][n] -------------------
__global__ void k_out(int cur, float* __restrict__ out) {
    int i = blockIdx.x * 256 + threadIdx.x;
    int b = i >> 14, rem = i & 16383, n = rem >> 6, d = rem & 63;
    out[b*16384 + d*256 + n] = g_x[cur][i];
}

// ---------------- launch -----------------------------------------------------
extern "C" void kernel_launch(void* const* d_in, const int* in_sizes, int n_in,
                              void* d_out, int out_size) {
    const float* sym = (const float*)d_in[0];
    const float* Wq  = (const float*)d_in[1];
    const float* bq  = (const float*)d_in[2];
    const float* Wk  = (const float*)d_in[3];
    const float* bk  = (const float*)d_in[4];
    const float* W1  = (const float*)d_in[5];
    const float* b1  = (const float*)d_in[6];
    const float* W2  = (const float*)d_in[7];
    const float* b2  = (const float*)d_in[8];
    const float* Wg1 = (const float*)d_in[13];
    const float* bg1 = (const float*)d_in[14];
    const float* Wg2 = (const float*)d_in[15];
    const float* bg2 = (const float*)d_in[16];
    float* out = (float*)d_out;

    static int smem_set = 0;
    if (!smem_set) {
        cudaFuncSetAttribute(k_rule, cudaFuncAttributeMaxDynamicSharedMemorySize,
                             SMEM_BYTES);
        smem_set = 1;
    }

    k_init<<<BDN/256, 256>>>(sym);
    k_precM<<<(RR*DD*DD)/256, 256>>>(Wq, Wk);
    k_precUVC<<<RR, DD>>>(Wq, bq, Wk, bk);

    int cur = 0;
    for (int s = 0; s < STEPS; s++) {
        k_rule<<<BB*RR, 512, SMEM_BYTES>>>(cur, W1, b1, W2, b2, Wg1, bg1, Wg2, bg2);
        k_reduce<<<BDN/256, 256>>>(cur);
        cur ^= 1;
    }
    k_out<<<BDN/256, 256>>>(cur, out);
}

// round 5
// speedup vs baseline: 5.3974x; 1.0898x over previous
#include <cuda_runtime.h>
#include <cuda_bf16.h>
#include <cstdint>

#define BB 16
#define DD 64
#define NN 256
#define RR 32
#define HDIM 128
#define STEPS 5
#define BDN (BB*DD*NN)

// bf16 smem pitches (elements); byte pitch mod 128 == 16 -> conflict-free ldmatrix
#define XN_P 72    // x [n][d]      144 B
#define MT_P 72    // M^T [d2][d1]
#define W1_P 72    // W1^T [h][d]
#define W2_P 136   // W2^T [d][h]   272 B

// byte offsets into dynamic smem (16B aligned)
#define OFF_XN  0                        // 256*72*2  = 36864
#define OFF_M   36864                    // 64*72*2   =  9216
#define OFF_W1  46080                    // 128*72*2  = 18432
#define OFF_W2  64512                    // 64*136*2  = 17408
#define OFF_E   81920
#define OFF_F   82944
#define OFF_U   83968
#define OFF_V   84224
#define OFF_PL  84480
#define OFF_HI  84736
#define OFF_GT  85248
#define SMEM_BYTES 85376

// ---------------- device globals -------------------------------------------
__device__ float g_x[2][BDN];          // state, layout [b][n][d], fp32
__device__ float g_M[RR*DD*DD];
__device__ float g_u[RR*DD];
__device__ float g_v[RR*DD];
__device__ float g_c[RR];
__device__ float g_t[(size_t)RR*BDN];  // per-rule deltas [r][b][n][d]

// ---------------- helpers ---------------------------------------------------
__device__ __forceinline__ void ldsm4(uint32_t& r0, uint32_t& r1,
                                      uint32_t& r2, uint32_t& r3, uint32_t sa) {
    asm volatile("ldmatrix.sync.aligned.m8n8.x4.shared.b16 {%0,%1,%2,%3}, [%4];"
        : "=r"(r0), "=r"(r1), "=r"(r2), "=r"(r3) : "r"(sa));
}
__device__ __forceinline__ void ldsm4t(uint32_t& r0, uint32_t& r1,
                                       uint32_t& r2, uint32_t& r3, uint32_t sa) {
    asm volatile("ldmatrix.sync.aligned.m8n8.x4.trans.shared.b16 {%0,%1,%2,%3}, [%4];"
        : "=r"(r0), "=r"(r1), "=r"(r2), "=r"(r3) : "r"(sa));
}
__device__ __forceinline__ void mma16(float* c, const uint32_t* a,
                                      uint32_t b0, uint32_t b1) {
    asm volatile("mma.sync.aligned.m16n8k16.row.col.f32.bf16.bf16.f32 "
        "{%0,%1,%2,%3}, {%4,%5,%6,%7}, {%8,%9}, {%0,%1,%2,%3};"
        : "+f"(c[0]), "+f"(c[1]), "+f"(c[2]), "+f"(c[3])
        : "r"(a[0]), "r"(a[1]), "r"(a[2]), "r"(a[3]), "r"(b0), "r"(b1));
}
__device__ __forceinline__ uint32_t pbf2(float lo, float hi) {
    __nv_bfloat162 h = __floats2bfloat162_rn(lo, hi);
    return *reinterpret_cast<uint32_t*>(&h);
}

// ---------------- init: symbols [b][d][n] -> g_x[0] as [b][n][d] -------------
__global__ void k_init(const float* __restrict__ sym) {
    int i = blockIdx.x * 256 + threadIdx.x;
    int b = i >> 14, rem = i & 16383, n = rem >> 6, d = rem & 63;
    g_x[0][i] = sym[b*16384 + d*256 + n];
}

// ---------------- precompute M = Wq Wk^T ------------------------------------
__global__ void k_precM(const float* __restrict__ Wq, const float* __restrict__ Wk) {
    int i = blockIdx.x * 256 + threadIdx.x;
    int d2 = i & 63, d1 = (i >> 6) & 63, r = i >> 12;
    const float* a = Wq + (r*DD + d1) * HDIM;
    const float* bkk = Wk + (r*DD + d2) * HDIM;
    float s = 0.f;
#pragma unroll 8
    for (int h = 0; h < HDIM; h++) s = fmaf(a[h], bkk[h], s);
    g_M[i] = s;
}

__global__ void k_precUVC(const float* __restrict__ Wq, const float* __restrict__ bq,
                          const float* __restrict__ Wk, const float* __restrict__ bk) {
    int r = blockIdx.x, d = threadIdx.x;
    float su = 0.f, sv = 0.f;
    const float* wqr = Wq + (r*DD + d) * HDIM;
    const float* wkr = Wk + (r*DD + d) * HDIM;
    const float* bqr = bq + r * HDIM;
    const float* bkr = bk + r * HDIM;
#pragma unroll 8
    for (int h = 0; h < HDIM; h++) {
        su = fmaf(wqr[h], bkr[h], su);
        sv = fmaf(bqr[h], wkr[h], sv);
    }
    g_u[r*DD + d] = su;
    g_v[r*DD + d] = sv;
    if (d == 0) {
        float sc = 0.f;
        for (int h = 0; h < HDIM; h++) sc = fmaf(bqr[h], bkr[h], sc);
        g_c[r] = sc;
    }
}

// ---------------- fused per-(b,r) rule kernel (bf16 mma, reg-resident) -------
__global__ void __launch_bounds__(512, 1)
k_rule(int cur,
       const float* __restrict__ W1g, const float* __restrict__ b1g,
       const float* __restrict__ W2g, const float* __restrict__ b2g,
       const float* __restrict__ Wg1, const float* __restrict__ bg1,
       const float* __restrict__ Wg2, const float* __restrict__ bg2) {
    extern __shared__ char smb[];
    const uint32_t sbu = (uint32_t)__cvta_generic_to_shared(smb);
    __nv_bfloat16* xNb  = (__nv_bfloat16*)(smb + OFF_XN);
    __nv_bfloat16* Mtb  = (__nv_bfloat16*)(smb + OFF_M);
    __nv_bfloat16* W1tb = (__nv_bfloat16*)(smb + OFF_W1);
    __nv_bfloat16* W2tb = (__nv_bfloat16*)(smb + OFF_W2);
    float* eS    = (float*)(smb + OFF_E);
    float* fS    = (float*)(smb + OFF_F);
    float* uS    = (float*)(smb + OFF_U);
    float* vS    = (float*)(smb + OFF_V);
    float* poolS = (float*)(smb + OFF_PL);
    float* hidS  = (float*)(smb + OFF_HI);
    float* gateS = (float*)(smb + OFF_GT);

    const int t = threadIdx.x;
    const int lane = t & 31, w = t >> 5;
    const int g = lane >> 2, t4 = lane & 3;
    const int r = blockIdx.x & (RR - 1), b = blockIdx.x >> 5;
    const int row0 = w * 16;

    // ldmatrix lane offsets
    const int aRow = lane & 15;                            // A x4
    const int aKof = (lane >> 4) << 3;
    const int bRow = (lane & 7) + ((lane >> 4) << 3);      // B x4 (normal)
    const int bKof = ((lane >> 3) & 1) << 3;
    const int tR   = (lane & 7) + (((lane >> 3) & 1) << 3); // B x4 (trans)
    const int tC   = ((lane >> 4) & 1) << 3;

    const float* xg = g_x[cur] + (size_t)b * NN * DD;

    // ---- prologue: stage x, M^T, W1^T, W2^T, u, v --------------------------
    for (int j = t; j < NN*DD/2; j += 512) {
        int n = j >> 5, d2 = (j & 31) * 2;
        *(uint32_t*)(smb + OFF_XN + (n*XN_P + d2)*2) = pbf2(xg[n*DD + d2], xg[n*DD + d2 + 1]);
    }
    for (int i = t; i < DD*DD; i += 512) {
        int d1 = i >> 6, d2 = i & 63;
        Mtb[d2*MT_P + d1] = __float2bfloat16_rn(g_M[r*DD*DD + i]);
    }
    for (int i = t; i < DD*HDIM; i += 512) {
        int d = i >> 7, h = i & 127;
        W1tb[h*W1_P + d] = __float2bfloat16_rn(__ldg(&W1g[r*DD*HDIM + i]));
    }
    for (int i = t; i < HDIM*DD; i += 512) {
        int h = i >> 6, d = i & 63;
        W2tb[d*W2_P + h] = __float2bfloat16_rn(__ldg(&W2g[r*HDIM*DD + i]));
    }
    if (t < DD) { uS[t] = g_u[r*DD + t]; vS[t] = g_v[r*DD + t]; }
    __syncthreads();

    // ---- e/f per token (warps 0-7), pooled mean (warps 8-15) ---------------
    if (t < NN) {
        float ea = 0.f, fa = 0.f;
#pragma unroll 8
        for (int d = 0; d < DD; d++) {
            float xv = __bfloat162float(xNb[t*XN_P + d]);
            ea = fmaf(xv, uS[d], ea);
            fa = fmaf(xv, vS[d], fa);
        }
        eS[t] = ea; fS[t] = fa;
    } else {
        int idx = t - NN, d = idx >> 2, q = idx & 3;
        float s = 0.f;
#pragma unroll 8
        for (int n = q*64; n < q*64 + 64; n++) s += __bfloat162float(xNb[n*XN_P + d]);
        s += __shfl_xor_sync(~0u, s, 1);
        s += __shfl_xor_sync(~0u, s, 2);
        if (q == 0) poolS[d] = s * (1.f/NN);
    }
    __syncthreads();
    if (t < HDIM) {
        float acc = bg1[t];
#pragma unroll 8
        for (int d = 0; d < DD; d++) acc = fmaf(poolS[d], __ldg(&Wg1[d*HDIM + t]), acc);
        hidS[t] = fmaxf(acc, 0.f);
    }
    __syncthreads();
    if (t < RR) {
        float lg = bg2[t];
#pragma unroll 8
        for (int j = 0; j < HDIM; j++) lg = fmaf(hidS[j], __ldg(&Wg2[j*RR + t]), lg);
        float m = lg;
#pragma unroll
        for (int o = 16; o > 0; o >>= 1) m = fmaxf(m, __shfl_xor_sync(~0u, m, o));
        float e = __expf(lg - m), ss = e;
#pragma unroll
        for (int o = 16; o > 0; o >>= 1) ss += __shfl_xor_sync(~0u, ss, o);
        gateS[t] = e / ss;
    }
    __syncthreads();   // last block-wide sync: all smem read-only below

    // ---- Phase A: sx = X @ M -> registers, repack to A frags ----------------
    uint32_t asx[4][4];
    {
        uint32_t ax[4][4];
#pragma unroll
        for (int k0 = 0; k0 < 4; k0++)
            ldsm4(ax[k0][0], ax[k0][1], ax[k0][2], ax[k0][3],
                  sbu + OFF_XN + ((row0 + aRow)*XN_P + k0*16 + aKof)*2);
        float SA[8][4];
#pragma unroll
        for (int nt = 0; nt < 8; nt++)
#pragma unroll
            for (int i = 0; i < 4; i++) SA[nt][i] = 0.f;
#pragma unroll
        for (int k0 = 0; k0 < 4; k0++)
#pragma unroll
            for (int p = 0; p < 4; p++) {
                uint32_t b0, b1, b2, b3;
                ldsm4(b0, b1, b2, b3,
                      sbu + OFF_M + ((p*16 + bRow)*MT_P + k0*16 + bKof)*2);
                mma16(SA[2*p],   ax[k0], b0, b1);
                mma16(SA[2*p+1], ax[k0], b2, b3);
            }
#pragma unroll
        for (int j = 0; j < 4; j++) {
            asx[j][0] = pbf2(SA[2*j][0],   SA[2*j][1]);
            asx[j][1] = pbf2(SA[2*j][2],   SA[2*j][3]);
            asx[j][2] = pbf2(SA[2*j+1][0], SA[2*j+1][1]);
            asx[j][3] = pbf2(SA[2*j+1][2], SA[2*j+1][3]);
        }
    }

    // ---- Phase B: flash attention, fully register-resident ------------------
    float CA[8][4];
    float Mr[2] = {-1e30f, -1e30f}, Lr[2] = {0.f, 0.f};
#pragma unroll
    for (int nt = 0; nt < 8; nt++)
#pragma unroll
        for (int i = 0; i < 4; i++) CA[nt][i] = 0.f;
    {
        const float cc = g_c[r];
        const float scl = 0.08838834764831845f;  // 1/sqrt(128)
#pragma unroll 1
        for (int j = 0; j < 4; j++) {
            const int mb = j * 64;
            float SB[8][4];
#pragma unroll
            for (int nt = 0; nt < 8; nt++)
#pragma unroll
                for (int i = 0; i < 4; i++) SB[nt][i] = 0.f;
#pragma unroll
            for (int k0 = 0; k0 < 4; k0++)
#pragma unroll
                for (int p = 0; p < 4; p++) {
                    uint32_t b0, b1, b2, b3;
                    ldsm4(b0, b1, b2, b3,
                          sbu + OFF_XN + ((mb + p*16 + bRow)*XN_P + k0*16 + bKof)*2);
                    mma16(SB[2*p],   asx[k0], b0, b1);
                    mma16(SB[2*p+1], asx[k0], b2, b3);
                }
            // bias + online softmax
#pragma unroll
            for (int hb = 0; hb < 2; hb++) {
                float er = eS[row0 + hb*8 + g] + cc;
                float mx = -1e30f;
#pragma unroll
                for (int nt = 0; nt < 8; nt++)
#pragma unroll
                    for (int i2 = 0; i2 < 2; i2++) {
                        float v = (SB[nt][hb*2 + i2] + er
                                   + fS[mb + nt*8 + 2*t4 + i2]) * scl;
                        SB[nt][hb*2 + i2] = v;
                        mx = fmaxf(mx, v);
                    }
                mx = fmaxf(mx, __shfl_xor_sync(~0u, mx, 1));
                mx = fmaxf(mx, __shfl_xor_sync(~0u, mx, 2));
                float Mn = fmaxf(Mr[hb], mx);
                float rs = __expf(Mr[hb] - Mn);
                Mr[hb] = Mn;
                float ls = 0.f;
#pragma unroll
                for (int nt = 0; nt < 8; nt++)
#pragma unroll
                    for (int i2 = 0; i2 < 2; i2++) {
                        float p = __expf(SB[nt][hb*2 + i2] - Mn);
                        SB[nt][hb*2 + i2] = p;
                        ls += p;
                    }
                ls += __shfl_xor_sync(~0u, ls, 1);
                ls += __shfl_xor_sync(~0u, ls, 2);
                Lr[hb] = Lr[hb]*rs + ls;
#pragma unroll
                for (int nt = 0; nt < 8; nt++) {
                    CA[nt][hb*2]     *= rs;
                    CA[nt][hb*2 + 1] *= rs;
                }
            }
            // repack P -> A frags (no smem!)
            uint32_t ap[4][4];
#pragma unroll
            for (int q = 0; q < 4; q++) {
                ap[q][0] = pbf2(SB[2*q][0],   SB[2*q][1]);
                ap[q][1] = pbf2(SB[2*q][2],   SB[2*q][3]);
                ap[q][2] = pbf2(SB[2*q+1][0], SB[2*q+1][1]);
                ap[q][3] = pbf2(SB[2*q+1][2], SB[2*q+1][3]);
            }
            // CTX += P @ X(rows mb..mb+63), B = X^T via trans ldmatrix
#pragma unroll
            for (int k0 = 0; k0 < 4; k0++)
#pragma unroll
                for (int p = 0; p < 4; p++) {
                    uint32_t b0, b1, b2, b3;
                    ldsm4t(b0, b1, b2, b3,
                           sbu + OFF_XN + ((mb + k0*16 + tR)*XN_P + p*16 + tC)*2);
                    mma16(CA[2*p],   ap[k0], b0, b1);
                    mma16(CA[2*p+1], ap[k0], b2, b3);
                }
        }
    }
    // normalize ctx, repack to A frags
    uint32_t actx[4][4];
    {
        float i0 = 1.f / Lr[0], i1 = 1.f / Lr[1];
#pragma unroll
        for (int q = 0; q < 4; q++) {
            actx[q][0] = pbf2(CA[2*q][0]*i0,   CA[2*q][1]*i0);
            actx[q][1] = pbf2(CA[2*q][2]*i1,   CA[2*q][3]*i1);
            actx[q][2] = pbf2(CA[2*q+1][0]*i0, CA[2*q+1][1]*i0);
            actx[q][3] = pbf2(CA[2*q+1][2]*i1, CA[2*q+1][3]*i1);
        }
    }

    // ---- Phase C: T = relu(ctx@W1 + b1)@W2, 16-h chunks, reg-resident ------
    {
        float TA[8][4];
#pragma unroll
        for (int nt = 0; nt < 8; nt++)
#pragma unroll
            for (int i = 0; i < 4; i++) TA[nt][i] = 0.f;
#pragma unroll 1
        for (int ck = 0; ck < 8; ck++) {
            const int h0 = ck * 16;
            float HA[2][4];
#pragma unroll
            for (int q = 0; q < 2; q++)
#pragma unroll
                for (int i = 0; i < 4; i++) HA[q][i] = 0.f;
#pragma unroll
            for (int k0 = 0; k0 < 4; k0++) {
                uint32_t b0, b1, b2, b3;
                ldsm4(b0, b1, b2, b3,
                      sbu + OFF_W1 + ((h0 + bRow)*W1_P + k0*16 + bKof)*2);
                mma16(HA[0], actx[k0], b0, b1);
                mma16(HA[1], actx[k0], b2, b3);
            }
            // bias + relu + repack H -> A frags
            uint32_t ah[4];
            {
                int hcA = h0 + 2*t4;
                float bA0 = __ldg(&b1g[r*HDIM + hcA]);
                float bA1 = __ldg(&b1g[r*HDIM + hcA + 1]);
                int hcB = h0 + 8 + 2*t4;
                float bB0 = __ldg(&b1g[r*HDIM + hcB]);
                float bB1 = __ldg(&b1g[r*HDIM + hcB + 1]);
                ah[0] = pbf2(fmaxf(HA[0][0] + bA0, 0.f), fmaxf(HA[0][1] + bA1, 0.f));
                ah[1] = pbf2(fmaxf(HA[0][2] + bA0, 0.f), fmaxf(HA[0][3] + bA1, 0.f));
                ah[2] = pbf2(fmaxf(HA[1][0] + bB0, 0.f), fmaxf(HA[1][1] + bB1, 0.f));
                ah[3] = pbf2(fmaxf(HA[1][2] + bB0, 0.f), fmaxf(HA[1][3] + bB1, 0.f));
            }
#pragma unroll
            for (int p = 0; p < 4; p++) {
                uint32_t b0, b1, b2, b3;
                ldsm4(b0, b1, b2, b3,
                      sbu + OFF_W2 + ((p*16 + bRow)*W2_P + h0 + bKof)*2);
                mma16(TA[2*p],   ah, b0, b1);
                mma16(TA[2*p+1], ah, b2, b3);
            }
        }
        // ---- epilogue: g_t[r][b][n][d] = gate * (T + b2) -------------------
        const float gv = gateS[r];
        float* outp = g_t + ((size_t)(r*BB + b)) * DD * NN;
#pragma unroll
        for (int nt = 0; nt < 8; nt++) {
            int d0 = nt*8 + 2*t4;
            float b20 = __ldg(&b2g[r*DD + d0]);
            float b21 = __ldg(&b2g[r*DD + d0 + 1]);
            float2 v0 = make_float2((TA[nt][0] + b20)*gv, (TA[nt][1] + b21)*gv);
            float2 v1 = make_float2((TA[nt][2] + b20)*gv, (TA[nt][3] + b21)*gv);
            *(float2*)(outp + (row0 + g)*DD + d0)     = v0;
            *(float2*)(outp + (row0 + 8 + g)*DD + d0) = v1;
        }
    }
}

// ---------------- deterministic reduction over rules + residual --------------
__global__ void k_reduce(int cur) {
    int i = blockIdx.x * 256 + threadIdx.x;
    float s = g_x[cur][i];
#pragma unroll
    for (int rr = 0; rr < RR; rr++) s += __ldg(&g_t[(size_t)rr * BDN + i]);
    g_x[cur ^ 1][i] = s;
}

// ---------------- writeback: [b][n][d] -> output [b][d][n] -------------------
__global__ void k_out(int cur, float* __restrict__ out) {
    int i = blockIdx.x * 256 + threadIdx.x;
    int b = i >> 14, rem = i & 16383, n = rem >> 6, d = rem & 63;
    out[b*16384 + d*256 + n] = g_x[cur][i];
}

// ---------------- launch -----------------------------------------------------
extern "C" void kernel_launch(void* const* d_in, const int* in_sizes, int n_in,
                              void* d_out, int out_size) {
    const float* sym = (const float*)d_in[0];
    const float* Wq  = (const float*)d_in[1];
    const float* bq  = (const float*)d_in[2];
    const float* Wk  = (const float*)d_in[3];
    const float* bk  = (const float*)d_in[4];
    const float* W1  = (const float*)d_in[5];
    const float* b1  = (const float*)d_in[6];
    const float* W2  = (const float*)d_in[7];
    const float* b2  = (const float*)d_in[8];
    const float* Wg1 = (const float*)d_in[13];
    const float* bg1 = (const float*)d_in[14];
    const float* Wg2 = (const float*)d_in[15];
    const float* bg2 = (const float*)d_in[16];
    float* out = (float*)d_out;

    static int smem_set = 0;
    if (!smem_set) {
        cudaFuncSetAttribute(k_rule, cudaFuncAttributeMaxDynamicSharedMemorySize,
                             SMEM_BYTES);
        smem_set = 1;
    }

    k_init<<<BDN/256, 256>>>(sym);
    k_precM<<<(RR*DD*DD)/256, 256>>>(Wq, Wk);
    k_precUVC<<<RR, DD>>>(Wq, bq, Wk, bk);

    int cur = 0;
    for (int s = 0; s < STEPS; s++) {
        k_rule<<<BB*RR, 512, SMEM_BYTES>>>(cur, W1, b1, W2, b2, Wg1, bg1, Wg2, bg2);
        k_reduce<<<BDN/256, 256>>>(cur);
        cur ^= 1;
    }
    k_out<<<BDN/256, 256>>>(cur, out);
}

// round 6
// speedup vs baseline: 5.6729x; 1.0510x over previous
#include <cuda_runtime.h>
#include <cuda_bf16.h>
#include <cstdint>

#define BB 16
#define DD 64
#define NN 256
#define RR 32
#define HDIM 128
#define STEPS 5
#define BDN (BB*DD*NN)

// bf16 smem pitches (elements); byte pitch mod 128 == 16 -> conflict-free ldmatrix
#define XN_P 72    // x [n][d]      144 B
#define MT_P 72    // M^T [d2][d1]
#define W1_P 72    // W1^T [h][d]
#define W2_P 136   // W2^T [d][h]   272 B

// byte offsets into dynamic smem (16B aligned)
#define OFF_XN  0                        // 256*72*2  = 36864
#define OFF_M   36864                    // 64*72*2   =  9216
#define OFF_W1  46080                    // 128*72*2  = 18432
#define OFF_W2  64512                    // 64*136*2  = 17408
#define OFF_E   81920
#define OFF_F   82944
#define OFF_U   83968
#define OFF_V   84224
#define OFF_PL  84480
#define OFF_HI  84736
#define OFF_GT  85248
#define SMEM_BYTES 85376

// 1/sqrt(128) * log2(e): softmax done in exp2 domain
#define SCL2 0.1275187959554910f

// ---------------- device globals -------------------------------------------
__device__ float g_x[2][BDN];          // state, layout [b][n][d], fp32
__device__ float g_M[RR*DD*DD];
__device__ float g_u[RR*DD];
__device__ float g_v[RR*DD];
__device__ float g_c[RR];
__device__ float g_t[(size_t)RR*BDN];  // per-rule deltas [r][b][n][d]

// ---------------- helpers ---------------------------------------------------
__device__ __forceinline__ void ldsm4(uint32_t& r0, uint32_t& r1,
                                      uint32_t& r2, uint32_t& r3, uint32_t sa) {
    asm volatile("ldmatrix.sync.aligned.m8n8.x4.shared.b16 {%0,%1,%2,%3}, [%4];"
        : "=r"(r0), "=r"(r1), "=r"(r2), "=r"(r3) : "r"(sa));
}
__device__ __forceinline__ void ldsm4t(uint32_t& r0, uint32_t& r1,
                                       uint32_t& r2, uint32_t& r3, uint32_t sa) {
    asm volatile("ldmatrix.sync.aligned.m8n8.x4.trans.shared.b16 {%0,%1,%2,%3}, [%4];"
        : "=r"(r0), "=r"(r1), "=r"(r2), "=r"(r3) : "r"(sa));
}
__device__ __forceinline__ void mma16(float* c, const uint32_t* a,
                                      uint32_t b0, uint32_t b1) {
    asm volatile("mma.sync.aligned.m16n8k16.row.col.f32.bf16.bf16.f32 "
        "{%0,%1,%2,%3}, {%4,%5,%6,%7}, {%8,%9}, {%0,%1,%2,%3};"
        : "+f"(c[0]), "+f"(c[1]), "+f"(c[2]), "+f"(c[3])
        : "r"(a[0]), "r"(a[1]), "r"(a[2]), "r"(a[3]), "r"(b0), "r"(b1));
}
__device__ __forceinline__ uint32_t pbf2(float lo, float hi) {
    __nv_bfloat162 h = __floats2bfloat162_rn(lo, hi);
    return *reinterpret_cast<uint32_t*>(&h);
}
__device__ __forceinline__ float ex2(float x) {
    float y; asm("ex2.approx.f32 %0, %1;" : "=f"(y) : "f"(x)); return y;
}

// ---------------- init: symbols [b][d][n] -> g_x[0] as [b][n][d] -------------
__global__ void k_init(const float* __restrict__ sym) {
    int i = blockIdx.x * 256 + threadIdx.x;
    int b = i >> 14, rem = i & 16383, n = rem >> 6, d = rem & 63;
    g_x[0][i] = sym[b*16384 + d*256 + n];
}

// ---------------- precompute M = Wq Wk^T ------------------------------------
__global__ void k_precM(const float* __restrict__ Wq, const float* __restrict__ Wk) {
    int i = blockIdx.x * 256 + threadIdx.x;
    int d2 = i & 63, d1 = (i >> 6) & 63, r = i >> 12;
    const float* a = Wq + (r*DD + d1) * HDIM;
    const float* bkk = Wk + (r*DD + d2) * HDIM;
    float s = 0.f;
#pragma unroll 8
    for (int h = 0; h < HDIM; h++) s = fmaf(a[h], bkk[h], s);
    g_M[i] = s;
}

__global__ void k_precUVC(const float* __restrict__ Wq, const float* __restrict__ bq,
                          const float* __restrict__ Wk, const float* __restrict__ bk) {
    int r = blockIdx.x, d = threadIdx.x;
    float su = 0.f, sv = 0.f;
    const float* wqr = Wq + (r*DD + d) * HDIM;
    const float* wkr = Wk + (r*DD + d) * HDIM;
    const float* bqr = bq + r * HDIM;
    const float* bkr = bk + r * HDIM;
#pragma unroll 8
    for (int h = 0; h < HDIM; h++) {
        su = fmaf(wqr[h], bkr[h], su);
        sv = fmaf(bqr[h], wkr[h], sv);
    }
    g_u[r*DD + d] = su;
    g_v[r*DD + d] = sv;
    if (d == 0) {
        float sc = 0.f;
        for (int h = 0; h < HDIM; h++) sc = fmaf(bqr[h], bkr[h], sc);
        g_c[r] = sc;
    }
}

// ---------------- fused per-(b,r) rule kernel (bf16 mma, reg-resident) -------
__global__ void __launch_bounds__(512, 1)
k_rule(int cur,
       const float* __restrict__ W1g, const float* __restrict__ b1g,
       const float* __restrict__ W2g, const float* __restrict__ b2g,
       const float* __restrict__ Wg1, const float* __restrict__ bg1,
       const float* __restrict__ Wg2, const float* __restrict__ bg2) {
    extern __shared__ char smb[];
    const uint32_t sbu = (uint32_t)__cvta_generic_to_shared(smb);
    __nv_bfloat16* xNb  = (__nv_bfloat16*)(smb + OFF_XN);
    __nv_bfloat16* Mtb  = (__nv_bfloat16*)(smb + OFF_M);
    __nv_bfloat16* W1tb = (__nv_bfloat16*)(smb + OFF_W1);
    __nv_bfloat16* W2tb = (__nv_bfloat16*)(smb + OFF_W2);
    float* eS    = (float*)(smb + OFF_E);    // (e + c) * SCL2 per query row
    float* fS    = (float*)(smb + OFF_F);    // f * SCL2 per key col
    float* uS    = (float*)(smb + OFF_U);
    float* vS    = (float*)(smb + OFF_V);
    float* poolS = (float*)(smb + OFF_PL);
    float* hidS  = (float*)(smb + OFF_HI);
    float* gateS = (float*)(smb + OFF_GT);

    const int t = threadIdx.x;
    const int lane = t & 31, w = t >> 5;
    const int g = lane >> 2, t4 = lane & 3;
    const int r = blockIdx.x & (RR - 1), b = blockIdx.x >> 5;
    const int row0 = w * 16;

    // ldmatrix lane offsets
    const int aRow = lane & 15;                            // A x4
    const int aKof = (lane >> 4) << 3;
    const int bRow = (lane & 7) + ((lane >> 4) << 3);      // B x4 (normal)
    const int bKof = ((lane >> 3) & 1) << 3;
    const int tR   = (lane & 7) + (((lane >> 3) & 1) << 3); // B x4 (trans)
    const int tC   = ((lane >> 4) & 1) << 3;

    const float* xg = g_x[cur] + (size_t)b * NN * DD;

    // ---- prologue: stage x, M^T, W1^T, W2^T, u, v --------------------------
    for (int j = t; j < NN*DD/2; j += 512) {
        int n = j >> 5, d2 = (j & 31) * 2;
        *(uint32_t*)(smb + OFF_XN + (n*XN_P + d2)*2) = pbf2(xg[n*DD + d2], xg[n*DD + d2 + 1]);
    }
    for (int i = t; i < DD*DD; i += 512) {
        int d1 = i >> 6, d2 = i & 63;
        Mtb[d2*MT_P + d1] = __float2bfloat16_rn(g_M[r*DD*DD + i]);
    }
    for (int i = t; i < DD*HDIM; i += 512) {
        int d = i >> 7, h = i & 127;
        W1tb[h*W1_P + d] = __float2bfloat16_rn(__ldg(&W1g[r*DD*HDIM + i]));
    }
    for (int i = t; i < HDIM*DD; i += 512) {
        int h = i >> 6, d = i & 63;
        W2tb[d*W2_P + h] = __float2bfloat16_rn(__ldg(&W2g[r*HDIM*DD + i]));
    }
    if (t < DD) { uS[t] = g_u[r*DD + t]; vS[t] = g_v[r*DD + t]; }
    __syncthreads();

    // ---- e/f per token (pre-scaled), pooled mean ---------------------------
    if (t < NN) {
        float ea = 0.f, fa = 0.f;
#pragma unroll 8
        for (int d = 0; d < DD; d++) {
            float xv = __bfloat162float(xNb[t*XN_P + d]);
            ea = fmaf(xv, uS[d], ea);
            fa = fmaf(xv, vS[d], fa);
        }
        eS[t] = (ea + g_c[r]) * SCL2;
        fS[t] = fa * SCL2;
    } else {
        int idx = t - NN, d = idx >> 2, q = idx & 3;
        float s = 0.f;
#pragma unroll 8
        for (int n = q*64; n < q*64 + 64; n++) s += __bfloat162float(xNb[n*XN_P + d]);
        s += __shfl_xor_sync(~0u, s, 1);
        s += __shfl_xor_sync(~0u, s, 2);
        if (q == 0) poolS[d] = s * (1.f/NN);
    }
    __syncthreads();
    if (t < HDIM) {
        float acc = bg1[t];
#pragma unroll 8
        for (int d = 0; d < DD; d++) acc = fmaf(poolS[d], __ldg(&Wg1[d*HDIM + t]), acc);
        hidS[t] = fmaxf(acc, 0.f);
    }
    __syncthreads();
    if (t < RR) {
        float lg = bg2[t];
#pragma unroll 8
        for (int j = 0; j < HDIM; j++) lg = fmaf(hidS[j], __ldg(&Wg2[j*RR + t]), lg);
        float m = lg;
#pragma unroll
        for (int o = 16; o > 0; o >>= 1) m = fmaxf(m, __shfl_xor_sync(~0u, m, o));
        float e = __expf(lg - m), ss = e;
#pragma unroll
        for (int o = 16; o > 0; o >>= 1) ss += __shfl_xor_sync(~0u, ss, o);
        gateS[t] = e / ss;
    }
    __syncthreads();   // last block-wide sync: all smem read-only below

    // ---- Phase A: sx = X @ M -> registers, repack to A frags ----------------
    uint32_t asx[4][4];
    {
        uint32_t ax[4][4];
#pragma unroll
        for (int k0 = 0; k0 < 4; k0++)
            ldsm4(ax[k0][0], ax[k0][1], ax[k0][2], ax[k0][3],
                  sbu + OFF_XN + ((row0 + aRow)*XN_P + k0*16 + aKof)*2);
        float SA[8][4];
#pragma unroll
        for (int nt = 0; nt < 8; nt++)
#pragma unroll
            for (int i = 0; i < 4; i++) SA[nt][i] = 0.f;
#pragma unroll
        for (int k0 = 0; k0 < 4; k0++)
#pragma unroll
            for (int p = 0; p < 4; p++) {
                uint32_t b0, b1, b2, b3;
                ldsm4(b0, b1, b2, b3,
                      sbu + OFF_M + ((p*16 + bRow)*MT_P + k0*16 + bKof)*2);
                mma16(SA[2*p],   ax[k0], b0, b1);
                mma16(SA[2*p+1], ax[k0], b2, b3);
            }
#pragma unroll
        for (int j = 0; j < 4; j++) {
            asx[j][0] = pbf2(SA[2*j][0],   SA[2*j][1]);
            asx[j][1] = pbf2(SA[2*j][2],   SA[2*j][3]);
            asx[j][2] = pbf2(SA[2*j+1][0], SA[2*j+1][1]);
            asx[j][3] = pbf2(SA[2*j+1][2], SA[2*j+1][3]);
        }
    }

    // ---- Phase B: attention, max-free softmax (exp2 domain) -----------------
    float CA[8][4];
    float Lr[2] = {0.f, 0.f};
#pragma unroll
    for (int nt = 0; nt < 8; nt++)
#pragma unroll
        for (int i = 0; i < 4; i++) CA[nt][i] = 0.f;
    {
#pragma unroll 1
        for (int j = 0; j < 4; j++) {
            const int mb = j * 64;
            float SB[8][4];
#pragma unroll
            for (int nt = 0; nt < 8; nt++)
#pragma unroll
                for (int i = 0; i < 4; i++) SB[nt][i] = 0.f;
#pragma unroll
            for (int k0 = 0; k0 < 4; k0++)
#pragma unroll
                for (int p = 0; p < 4; p++) {
                    uint32_t b0, b1, b2, b3;
                    ldsm4(b0, b1, b2, b3,
                          sbu + OFF_XN + ((mb + p*16 + bRow)*XN_P + k0*16 + bKof)*2);
                    mma16(SB[2*p],   asx[k0], b0, b1);
                    mma16(SB[2*p+1], asx[k0], b2, b3);
                }
            // p = exp2(S*SCL2 + e' + f');  Lr += p   (no max, no shuffles)
#pragma unroll
            for (int hb = 0; hb < 2; hb++) {
                const float er = eS[row0 + hb*8 + g];
#pragma unroll
                for (int nt = 0; nt < 8; nt++)
#pragma unroll
                    for (int i2 = 0; i2 < 2; i2++) {
                        float ef = er + fS[mb + nt*8 + 2*t4 + i2];
                        float p = ex2(fmaf(SB[nt][hb*2 + i2], SCL2, ef));
                        SB[nt][hb*2 + i2] = p;
                        Lr[hb] += p;
                    }
            }
            // repack P -> A frags
            uint32_t ap[4][4];
#pragma unroll
            for (int q = 0; q < 4; q++) {
                ap[q][0] = pbf2(SB[2*q][0],   SB[2*q][1]);
                ap[q][1] = pbf2(SB[2*q][2],   SB[2*q][3]);
                ap[q][2] = pbf2(SB[2*q+1][0], SB[2*q+1][1]);
                ap[q][3] = pbf2(SB[2*q+1][2], SB[2*q+1][3]);
            }
            // CTX += P @ X(rows mb..mb+63), B = X^T via trans ldmatrix
#pragma unroll
            for (int k0 = 0; k0 < 4; k0++)
#pragma unroll
                for (int p = 0; p < 4; p++) {
                    uint32_t b0, b1, b2, b3;
                    ldsm4t(b0, b1, b2, b3,
                           sbu + OFF_XN + ((mb + k0*16 + tR)*XN_P + p*16 + tC)*2);
                    mma16(CA[2*p],   ap[k0], b0, b1);
                    mma16(CA[2*p+1], ap[k0], b2, b3);
                }
        }
    }
    // row-sum reduce (once), normalize ctx, repack to A frags
    uint32_t actx[4][4];
    {
#pragma unroll
        for (int hb = 0; hb < 2; hb++) {
            Lr[hb] += __shfl_xor_sync(~0u, Lr[hb], 1);
            Lr[hb] += __shfl_xor_sync(~0u, Lr[hb], 2);
        }
        float i0 = 1.f / Lr[0], i1 = 1.f / Lr[1];
#pragma unroll
        for (int q = 0; q < 4; q++) {
            actx[q][0] = pbf2(CA[2*q][0]*i0,   CA[2*q][1]*i0);
            actx[q][1] = pbf2(CA[2*q][2]*i1,   CA[2*q][3]*i1);
            actx[q][2] = pbf2(CA[2*q+1][0]*i0, CA[2*q+1][1]*i0);
            actx[q][3] = pbf2(CA[2*q+1][2]*i1, CA[2*q+1][3]*i1);
        }
    }

    // ---- Phase C: T = relu(ctx@W1 + b1)@W2, 32-h chunks --------------------
    {
        float TA[8][4];
#pragma unroll
        for (int nt = 0; nt < 8; nt++)
#pragma unroll
            for (int i = 0; i < 4; i++) TA[nt][i] = 0.f;
#pragma unroll 1
        for (int ck = 0; ck < 4; ck++) {
            const int h0 = ck * 32;
            float HA[4][4];
#pragma unroll
            for (int q = 0; q < 4; q++)
#pragma unroll
                for (int i = 0; i < 4; i++) HA[q][i] = 0.f;
#pragma unroll
            for (int k0 = 0; k0 < 4; k0++) {
                uint32_t b0, b1, b2, b3, c0, c1, c2, c3;
                ldsm4(b0, b1, b2, b3,
                      sbu + OFF_W1 + ((h0 + bRow)*W1_P + k0*16 + bKof)*2);
                ldsm4(c0, c1, c2, c3,
                      sbu + OFF_W1 + ((h0 + 16 + bRow)*W1_P + k0*16 + bKof)*2);
                mma16(HA[0], actx[k0], b0, b1);
                mma16(HA[1], actx[k0], b2, b3);
                mma16(HA[2], actx[k0], c0, c1);
                mma16(HA[3], actx[k0], c2, c3);
            }
            // bias + relu + repack H -> A frags (two 16-h chunks)
            uint32_t ah[2][4];
#pragma unroll
            for (int hc = 0; hc < 2; hc++) {
                int base = h0 + hc*16;
                float bA0 = __ldg(&b1g[r*HDIM + base + 2*t4]);
                float bA1 = __ldg(&b1g[r*HDIM + base + 2*t4 + 1]);
                float bB0 = __ldg(&b1g[r*HDIM + base + 8 + 2*t4]);
                float bB1 = __ldg(&b1g[r*HDIM + base + 8 + 2*t4 + 1]);
                ah[hc][0] = pbf2(fmaxf(HA[2*hc][0] + bA0, 0.f),   fmaxf(HA[2*hc][1] + bA1, 0.f));
                ah[hc][1] = pbf2(fmaxf(HA[2*hc][2] + bA0, 0.f),   fmaxf(HA[2*hc][3] + bA1, 0.f));
                ah[hc][2] = pbf2(fmaxf(HA[2*hc+1][0] + bB0, 0.f), fmaxf(HA[2*hc+1][1] + bB1, 0.f));
                ah[hc][3] = pbf2(fmaxf(HA[2*hc+1][2] + bB0, 0.f), fmaxf(HA[2*hc+1][3] + bB1, 0.f));
            }
#pragma unroll
            for (int p = 0; p < 4; p++) {
                uint32_t b0, b1, b2, b3, c0, c1, c2, c3;
                ldsm4(b0, b1, b2, b3,
                      sbu + OFF_W2 + ((p*16 + bRow)*W2_P + h0 + bKof)*2);
                ldsm4(c0, c1, c2, c3,
                      sbu + OFF_W2 + ((p*16 + bRow)*W2_P + h0 + 16 + bKof)*2);
                mma16(TA[2*p],   ah[0], b0, b1);
                mma16(TA[2*p+1], ah[0], b2, b3);
                mma16(TA[2*p],   ah[1], c0, c1);
                mma16(TA[2*p+1], ah[1], c2, c3);
            }
        }
        // ---- epilogue: g_t[r][b][n][d] = gate * (T + b2) -------------------
        const float gv = gateS[r];
        float* outp = g_t + ((size_t)(r*BB + b)) * DD * NN;
#pragma unroll
        for (int nt = 0; nt < 8; nt++) {
            int d0 = nt*8 + 2*t4;
            float b20 = __ldg(&b2g[r*DD + d0]);
            float b21 = __ldg(&b2g[r*DD + d0 + 1]);
            float2 v0 = make_float2((TA[nt][0] + b20)*gv, (TA[nt][1] + b21)*gv);
            float2 v1 = make_float2((TA[nt][2] + b20)*gv, (TA[nt][3] + b21)*gv);
            *(float2*)(outp + (row0 + g)*DD + d0)     = v0;
            *(float2*)(outp + (row0 + 8 + g)*DD + d0) = v1;
        }
    }
}

// ---------------- deterministic reduction over rules + residual --------------
__global__ void k_reduce(int cur) {
    int i = blockIdx.x * 256 + threadIdx.x;
    float s = g_x[cur][i];
#pragma unroll
    for (int rr = 0; rr < RR; rr++) s += __ldg(&g_t[(size_t)rr * BDN + i]);
    g_x[cur ^ 1][i] = s;
}

// ---------------- writeback: [b][n][d] -> output [b][d][n] -------------------
__global__ void k_out(int cur, float* __restrict__ out) {
    int i = blockIdx.x * 256 + threadIdx.x;
    int b = i >> 14, rem = i & 16383, n = rem >> 6, d = rem & 63;
    out[b*16384 + d*256 + n] = g_x[cur][i];
}

// ---------------- launch -----------------------------------------------------
extern "C" void kernel_launch(void* const* d_in, const int* in_sizes, int n_in,
                              void* d_out, int out_size) {
    const float* sym = (const float*)d_in[0];
    const float* Wq  = (const float*)d_in[1];
    const float* bq  = (const float*)d_in[2];
    const float* Wk  = (const float*)d_in[3];
    const float* bk  = (const float*)d_in[4];
    const float* W1  = (const float*)d_in[5];
    const float* b1  = (const float*)d_in[6];
    const float* W2  = (const float*)d_in[7];
    const float* b2  = (const float*)d_in[8];
    const float* Wg1 = (const float*)d_in[13];
    const float* bg1 = (const float*)d_in[14];
    const float* Wg2 = (const float*)d_in[15];
    const float* bg2 = (const float*)d_in[16];
    float* out = (float*)d_out;

    static int smem_set = 0;
    if (!smem_set) {
        cudaFuncSetAttribute(k_rule, cudaFuncAttributeMaxDynamicSharedMemorySize,
                             SMEM_BYTES);
        smem_set = 1;
    }

    k_init<<<BDN/256, 256>>>(sym);
    k_precM<<<(RR*DD*DD)/256, 256>>>(Wq, Wk);
    k_precUVC<<<RR, DD>>>(Wq, bq, Wk, bk);

    int cur = 0;
    for (int s = 0; s < STEPS; s++) {
        k_rule<<<BB*RR, 512, SMEM_BYTES>>>(cur, W1, b1, W2, b2, Wg1, bg1, Wg2, bg2);
        k_reduce<<<BDN/256, 256>>>(cur);
        cur ^= 1;
    }
    k_out<<<BDN/256, 256>>>(cur, out);
}